// round 7
// baseline (speedup 1.0000x reference)
#include <cuda_runtime.h>
#include <cuda_bf16.h>
#include <stdint.h>
#include <math.h>

#define BATCH 2
#define SEQ   8192
#define DIM   1024
#define HEADS 8
#define DH    64
#define HDH   512
#define WIN   64
#define NW    (SEQ/WIN)
#define NQ    1024
#define NKV   2048
#define NROWS (BATCH*SEQ)
#define NSPLIT 4
#define KV_PER_SPLIT (NKV/NSPLIT)

// ---------------- scratch ----------------
__device__ float g_xn  [NROWS*DIM];
__device__ float g_qkv [NROWS*3*HDH];
__device__ float g_lo  [NROWS*HDH];
__device__ float g_s   [2][NROWS];
__device__ int   g_sel [2][BATCH][NKV];
__device__ float g_xqn [BATCH*NQ*DIM];
__device__ float g_xkvn[BATCH*NKV*DIM];
__device__ float g_qh  [BATCH*NQ*HDH];
__device__ float g_kvh [BATCH*NKV*2*HDH];
__device__ float g_oh  [BATCH*NQ*HDH];
__device__ float g_ro  [BATCH*NQ*DIM];
__device__ float g_pm  [BATCH*HEADS*NSPLIT*NQ];
__device__ float g_pl  [BATCH*HEADS*NSPLIT*NQ];
__device__ float g_po  [(size_t)BATCH*HEADS*NSPLIT*NQ*DH];

// ---------------- reductions ----------------
__device__ __forceinline__ float blockSum(float v){
    __shared__ float sh[33];
    int lane = threadIdx.x & 31, wid = threadIdx.x >> 5;
    #pragma unroll
    for (int o=16;o>0;o>>=1) v += __shfl_down_sync(0xffffffffu, v, o);
    __syncthreads();
    if (lane==0) sh[wid]=v;
    __syncthreads();
    if (wid==0){
        float r = (lane < (blockDim.x>>5)) ? sh[lane] : 0.f;
        #pragma unroll
        for (int o=16;o>0;o>>=1) r += __shfl_down_sync(0xffffffffu, r, o);
        if (lane==0) sh[32]=r;
    }
    __syncthreads();
    return sh[32];
}

__device__ __forceinline__ double blockSumD(double v){
    __shared__ double shd[33];
    int lane = threadIdx.x & 31, wid = threadIdx.x >> 5;
    #pragma unroll
    for (int o=16;o>0;o>>=1) v += __shfl_down_sync(0xffffffffu, v, o);
    __syncthreads();
    if (lane==0) shd[wid]=v;
    __syncthreads();
    if (wid==0){
        double r = (lane < (blockDim.x>>5)) ? shd[lane] : 0.0;
        #pragma unroll
        for (int o=16;o>0;o>>=1) r += __shfl_down_sync(0xffffffffu, r, o);
        if (lane==0) shd[32]=r;
    }
    __syncthreads();
    return shd[32];
}

// ---------------- fused layernorm + routing logits ----------------
__global__ __launch_bounds__(256) void k_pre(const float* __restrict__ x,
                                             const float* __restrict__ ln_g,
                                             const float* __restrict__ ln_b,
                                             const float* __restrict__ rt_q,
                                             const float* __restrict__ rt_kv){
    __shared__ float xr[DIM];
    size_t row = blockIdx.x;
    const float* xp = x + row*DIM;
    float s=0.f, s2=0.f, dq=0.f, dk=0.f;
    for (int d=threadIdx.x; d<DIM; d+=256){
        float v = xp[d]; xr[d]=v;
        s += v; s2 += v*v; dq += v*rt_q[d]; dk += v*rt_kv[d];
    }
    s  = blockSum(s);
    s2 = blockSum(s2);
    dq = blockSum(dq);
    dk = blockSum(dk);
    if (threadIdx.x==0){ g_s[0][row]=dq; g_s[1][row]=dk; }
    float m    = s * (1.f/DIM);
    float var  = s2 * (1.f/DIM) - m*m;
    float rstd = rsqrtf(var + 1e-5f);
    for (int d=threadIdx.x; d<DIM; d+=256)
        g_xn[row*DIM+d] = (xr[d]-m)*rstd*ln_g[d] + ln_b[d];
}

// ================= tensor-core GEMM (bf16x2 split, fp32-accurate) =========
__device__ __forceinline__ void split2(float x, float y, uint32_t& hi, uint32_t& lo){
    __nv_bfloat16 hx = __float2bfloat16_rn(x), hy = __float2bfloat16_rn(y);
    float rx = x - __bfloat162float(hx);
    float ry = y - __bfloat162float(hy);
    __nv_bfloat16 lx = __float2bfloat16_rn(rx), ly = __float2bfloat16_rn(ry);
    hi = (uint32_t)__bfloat16_as_ushort(hx) | ((uint32_t)__bfloat16_as_ushort(hy)<<16);
    lo = (uint32_t)__bfloat16_as_ushort(lx) | ((uint32_t)__bfloat16_as_ushort(ly)<<16);
}

#define LDM_X4(r0,r1,r2,r3,p) \
    asm volatile("ldmatrix.sync.aligned.m8n8.x4.shared.b16 {%0,%1,%2,%3},[%4];" \
        : "=r"(r0),"=r"(r1),"=r"(r2),"=r"(r3) : "r"(p))
#define LDM_X2T(r0,r1,p) \
    asm volatile("ldmatrix.sync.aligned.m8n8.x2.trans.shared.b16 {%0,%1},[%2];" \
        : "=r"(r0),"=r"(r1) : "r"(p))
#define MMA16816(d,a0,a1,a2,a3,b0,b1) \
    asm volatile("mma.sync.aligned.m16n8k16.row.col.f32.bf16.bf16.f32 " \
        "{%0,%1,%2,%3},{%4,%5,%6,%7},{%8,%9},{%0,%1,%2,%3};" \
        : "+f"(d[0]),"+f"(d[1]),"+f"(d[2]),"+f"(d[3]) \
        : "r"(a0),"r"(a1),"r"(a2),"r"(a3),"r"(b0),"r"(b1))

#define A_LD 24
#define B_LD 136

__global__ __launch_bounds__(256,2) void gemm_tc(int M,int N,int K,
                                                 const float* __restrict__ A,
                                                 const float* __restrict__ B,
                                                 float* __restrict__ C,
                                                 const float* __restrict__ bias){
    __shared__ __nv_bfloat16 Ah[2][128][A_LD];
    __shared__ __nv_bfloat16 Al[2][128][A_LD];
    __shared__ __nv_bfloat16 Bh[2][16][B_LD];
    __shared__ __nv_bfloat16 Bl[2][16][B_LD];
    const int tid  = threadIdx.x;
    const int lane = tid & 31, wid = tid >> 5;
    const int wm = (wid>>2)*64;
    const int wn = (wid&3)*32;
    const size_t bx = blockIdx.x, by = blockIdx.y;
    const float* Ag = A + by*128*(size_t)K;
    const float* Bg = B + bx*128;
    const int ar = tid>>1, ac = (tid&1)*8;
    const int br = tid>>4, bc = (tid&15)*8;
    const int arow  = (lane&7) + ((lane>>3)&1)*8;
    const int acolb = (lane>>4)*8;
    const int bkrow = lane & 15;

    float acc[4][4][4];
    #pragma unroll
    for (int i=0;i<4;i++)
        #pragma unroll
        for (int j=0;j<4;j++)
            #pragma unroll
            for (int c=0;c<4;c++) acc[i][j][c]=0.f;

    const int nk = K >> 4;
    float4 pa0,pa1,pb0,pb1;
    {
        const float* Ap = Ag + (size_t)ar*K + ac;
        pa0 = *(const float4*)Ap; pa1 = *(const float4*)(Ap+4);
        const float* Bp = Bg + (size_t)br*N + bc;
        pb0 = *(const float4*)Bp; pb1 = *(const float4*)(Bp+4);
    }
    for (int t=0; t<nk; t++){
        const int buf = t & 1;
        {
            uint32_t h,l;
            split2(pa0.x,pa0.y,h,l); *(uint32_t*)&Ah[buf][ar][ac+0]=h; *(uint32_t*)&Al[buf][ar][ac+0]=l;
            split2(pa0.z,pa0.w,h,l); *(uint32_t*)&Ah[buf][ar][ac+2]=h; *(uint32_t*)&Al[buf][ar][ac+2]=l;
            split2(pa1.x,pa1.y,h,l); *(uint32_t*)&Ah[buf][ar][ac+4]=h; *(uint32_t*)&Al[buf][ar][ac+4]=l;
            split2(pa1.z,pa1.w,h,l); *(uint32_t*)&Ah[buf][ar][ac+6]=h; *(uint32_t*)&Al[buf][ar][ac+6]=l;
            split2(pb0.x,pb0.y,h,l); *(uint32_t*)&Bh[buf][br][bc+0]=h; *(uint32_t*)&Bl[buf][br][bc+0]=l;
            split2(pb0.z,pb0.w,h,l); *(uint32_t*)&Bh[buf][br][bc+2]=h; *(uint32_t*)&Bl[buf][br][bc+2]=l;
            split2(pb1.x,pb1.y,h,l); *(uint32_t*)&Bh[buf][br][bc+4]=h; *(uint32_t*)&Bl[buf][br][bc+4]=l;
            split2(pb1.z,pb1.w,h,l); *(uint32_t*)&Bh[buf][br][bc+6]=h; *(uint32_t*)&Bl[buf][br][bc+6]=l;
        }
        __syncthreads();
        if (t+1 < nk){
            const float* Ap = Ag + (size_t)ar*K + (t+1)*16 + ac;
            pa0 = *(const float4*)Ap; pa1 = *(const float4*)(Ap+4);
            const float* Bp = Bg + ((size_t)((t+1)*16 + br))*N + bc;
            pb0 = *(const float4*)Bp; pb1 = *(const float4*)(Bp+4);
        }
        uint32_t bhf[4][2], blf[4][2];
        #pragma unroll
        for (int nt=0;nt<4;nt++){
            uint32_t ph = (uint32_t)__cvta_generic_to_shared(&Bh[buf][bkrow][wn+nt*8]);
            LDM_X2T(bhf[nt][0],bhf[nt][1],ph);
            uint32_t pl = (uint32_t)__cvta_generic_to_shared(&Bl[buf][bkrow][wn+nt*8]);
            LDM_X2T(blf[nt][0],blf[nt][1],pl);
        }
        #pragma unroll
        for (int mt=0;mt<4;mt++){
            uint32_t ah0,ah1,ah2,ah3, al0,al1,al2,al3;
            uint32_t pA = (uint32_t)__cvta_generic_to_shared(&Ah[buf][wm+mt*16+arow][acolb]);
            LDM_X4(ah0,ah1,ah2,ah3,pA);
            uint32_t pAl = (uint32_t)__cvta_generic_to_shared(&Al[buf][wm+mt*16+arow][acolb]);
            LDM_X4(al0,al1,al2,al3,pAl);
            #pragma unroll
            for (int nt=0;nt<4;nt++){
                MMA16816(acc[mt][nt], ah0,ah1,ah2,ah3, bhf[nt][0],bhf[nt][1]);
                MMA16816(acc[mt][nt], ah0,ah1,ah2,ah3, blf[nt][0],blf[nt][1]);
                MMA16816(acc[mt][nt], al0,al1,al2,al3, bhf[nt][0],bhf[nt][1]);
            }
        }
        __syncthreads();
    }
    const int g = lane>>2, tq = lane&3;
    #pragma unroll
    for (int nt=0;nt<4;nt++){
        const int col = (int)bx*128 + wn + nt*8 + tq*2;
        float b0=0.f,b1=0.f;
        if (bias){ b0=bias[col]; b1=bias[col+1]; }
        #pragma unroll
        for (int mt=0;mt<4;mt++){
            const int row = (int)by*128 + wm + mt*16 + g;
            float2* p0 = (float2*)(C + (size_t)row*N + col);
            *p0 = make_float2(acc[mt][nt][0]+b0, acc[mt][nt][1]+b1);
            float2* p1 = (float2*)(C + (size_t)(row+8)*N + col);
            *p1 = make_float2(acc[mt][nt][2]+b0, acc[mt][nt][3]+b1);
        }
    }
}

// ---------------- light (windowed) attention: 4 lanes per query -----------
// 256 threads = 64 queries x 4 dim-subgroups of 16. Dot via 2x shfl_xor.
__global__ __launch_bounds__(256) void k_light(){
    const int w = blockIdx.x, h = blockIdx.y, b = blockIdx.z;
    const int tid = threadIdx.x;
    const int qi = tid >> 2;       // query within window
    const int ds = tid & 3;        // 16-dim subgroup
    __shared__ float4 ks4[WIN][16];
    __shared__ float4 vs4[WIN][16];
    const int n0 = w*WIN;
    const float* qp = g_qkv + ((size_t)(b*SEQ + n0 + qi))*(3*HDH) + h*DH + ds*16;
    float4 q4[4];
    #pragma unroll
    for (int c=0;c<4;c++){
        float4 v = *(const float4*)(qp + c*4);
        q4[c] = make_float4(v.x*0.125f, v.y*0.125f, v.z*0.125f, v.w*0.125f);
    }
    float m=-1e30f, l=0.f;
    float4 o4[4];
    #pragma unroll
    for (int c=0;c<4;c++) o4[c]=make_float4(0.f,0.f,0.f,0.f);
    for (int c=0;c<3;c++){
        const int wc = w-1+c;
        if (wc<0 || wc>=NW) continue;   // uniform across block
        __syncthreads();
        const float* kb = g_qkv + ((size_t)(b*SEQ + wc*WIN))*(3*HDH) + HDH + h*DH;
        #pragma unroll
        for (int j2=0;j2<4;j2++){
            ks4[qi][ds*4+j2] = *(const float4*)(kb + (size_t)qi*(3*HDH) + (ds*4+j2)*4);
            vs4[qi][ds*4+j2] = *(const float4*)(kb + (size_t)qi*(3*HDH) + HDH + (ds*4+j2)*4);
        }
        __syncthreads();
        for (int j=0;j<WIN;j++){
            float x0=0.f,x1=0.f,x2=0.f,x3=0.f;
            #pragma unroll
            for (int cc=0;cc<4;cc++){
                float4 k4 = ks4[j][ds*4+cc];
                x0 += q4[cc].x*k4.x; x1 += q4[cc].y*k4.y;
                x2 += q4[cc].z*k4.z; x3 += q4[cc].w*k4.w;
            }
            float xv = (x0+x1)+(x2+x3);
            xv += __shfl_xor_sync(0xffffffffu, xv, 1);
            xv += __shfl_xor_sync(0xffffffffu, xv, 2);
            float mn = fmaxf(m, xv);
            float f  = __expf(m-mn);
            float e  = __expf(xv-mn);
            l = l*f + e;
            #pragma unroll
            for (int cc=0;cc<4;cc++){
                float4 v4 = vs4[j][ds*4+cc];
                o4[cc].x = o4[cc].x*f + e*v4.x;
                o4[cc].y = o4[cc].y*f + e*v4.y;
                o4[cc].z = o4[cc].z*f + e*v4.z;
                o4[cc].w = o4[cc].w*f + e*v4.w;
            }
            m = mn;
        }
    }
    float inv = 1.f/l;
    float* op = g_lo + ((size_t)(b*SEQ + n0 + qi))*HDH + h*DH + ds*16;
    #pragma unroll
    for (int cc=0;cc<4;cc++)
        *(float4*)(op + cc*4) = make_float4(o4[cc].x*inv, o4[cc].y*inv,
                                            o4[cc].z*inv, o4[cc].w*inv);
}

// ---------------- routing: fixed point + radix top-k set selection --------
__global__ __launch_bounds__(1024) void k_route(){
    const int b = blockIdx.x, r = blockIdx.y;
    const int tid = threadIdx.x;
    const int cnt = (r==0) ? NQ : NKV;
    const float* s = g_s[r] + (size_t)b*SEQ;
    float sv[8];
    {
        float4 v0 = *(const float4*)(s + tid*8);
        float4 v1 = *(const float4*)(s + tid*8 + 4);
        sv[0]=v0.x; sv[1]=v0.y; sv[2]=v0.z; sv[3]=v0.w;
        sv[4]=v1.x; sv[5]=v1.y; sv[6]=v1.z; sv[7]=v1.w;
    }
    double E[8];
    #pragma unroll
    for (int i=0;i<8;i++) E[i] = exp((double)sv[i]);
    __shared__ double aSh;
    const double logk = (double)logf(r==0 ? 1152.0f : 2304.0f);
    double a = logk - (double)logf(8192.0f);
    for (int it=0; it<49; it++){
        double T = exp(-a);
        double tt=0.0;
        #pragma unroll
        for (int i=0;i<8;i++) tt += fmin(E[i], T);
        tt = blockSumD(tt);
        if (tid==0) aSh = logk - log(tt);
        __syncthreads();
        a = aSh;
        __syncthreads();
    }
    const float af = (float)a;
    uint32_t u[8];
    #pragma unroll
    for (int i=0;i<8;i++)
        u[i] = __float_as_uint(expf(fminf(sv[i]+af, 0.f)));
    __shared__ int hist[256];
    __shared__ uint32_t pbc; __shared__ int rbc;
    uint32_t prefix = 0; int remaining = cnt;
    for (int shift=24; shift>=0; shift-=8){
        for (int cc=tid; cc<256; cc+=1024) hist[cc]=0;
        __syncthreads();
        uint32_t pmask = (shift==24) ? 0u : (0xFFFFFFFFu << (shift+8));
        #pragma unroll
        for (int i=0;i<8;i++)
            if ((u[i] & pmask) == prefix)
                atomicAdd(&hist[(u[i]>>shift)&255], 1);
        __syncthreads();
        if (tid==0){
            int rem = remaining; uint32_t dig = 0;
            for (int d=255; d>=0; d--){
                int hv = hist[d];
                if (rem - hv <= 0){ dig = (uint32_t)d; break; }
                rem -= hv;
            }
            pbc = prefix | (dig<<shift);
            rbc = rem;
        }
        __syncthreads();
        prefix = pbc; remaining = rbc;
        __syncthreads();
    }
    const uint32_t ut = prefix;
    const int Cgt = cnt - remaining;
    __shared__ int sgt[1024], seqv[1024];
    int cgt=0, ceq=0;
    #pragma unroll
    for (int i=0;i<8;i++){
        if (u[i] > ut) cgt++;
        else if (u[i] == ut) ceq++;
    }
    sgt[tid]=cgt; seqv[tid]=ceq;
    __syncthreads();
    for (int off=1; off<1024; off<<=1){
        int a0=0,b0=0;
        if (tid>=off){ a0=sgt[tid-off]; b0=seqv[tid-off]; }
        __syncthreads();
        sgt[tid]+=a0; seqv[tid]+=b0;
        __syncthreads();
    }
    int gtPos = sgt[tid]-cgt;
    int eqPos = seqv[tid]-ceq;
    #pragma unroll
    for (int i=0;i<8;i++){
        const int idx = tid*8 + i;
        if (u[i] > ut){
            g_sel[r][b][gtPos++] = idx;
        } else if (u[i] == ut){
            int rk = eqPos++;
            if (rk < remaining) g_sel[r][b][Cgt + rk] = idx;
        }
    }
}

// ---------------- gather + rmsnorm ----------------
__global__ __launch_bounds__(256) void k_gather(const float* __restrict__ x,
                                                const float* __restrict__ rms_g,
                                                int route){
    const int j = blockIdx.x, b = blockIdx.y;
    const int cnt = route ? NKV : NQ;
    float* out = route ? g_xkvn : g_xqn;
    const int n = g_sel[route][b][j];
    const float* xp = x + ((size_t)(b*SEQ) + n)*DIM;
    float ss=0.f;
    for (int d=threadIdx.x; d<DIM; d+=256){ float v=xp[d]; ss += v*v; }
    ss = blockSum(ss);
    const float sc = 32.f / fmaxf(sqrtf(ss), 1e-12f);
    float* op = out + ((size_t)b*cnt + j)*DIM;
    for (int d=threadIdx.x; d<DIM; d+=256) op[d] = xp[d]*sc*rms_g[d];
}

// ---------------- heavy attention, split-KV partials: 4 lanes/query -------
__global__ __launch_bounds__(256) void k_heavy_part(const float* __restrict__ null_kv){
    const int qc = blockIdx.x, h = blockIdx.y;
    const int b  = blockIdx.z >> 2, sp = blockIdx.z & 3;
    const int tid = threadIdx.x;
    const int qi = tid >> 2;
    const int ds = tid & 3;
    __shared__ float4 ks4[64][16];
    __shared__ float4 vs4[64][16];
    const int q = qc*64 + qi;
    const float* qp = g_qh + ((size_t)(b*NQ + q))*HDH + h*DH + ds*16;
    float4 q4[4];
    #pragma unroll
    for (int c=0;c<4;c++){
        float4 v = *(const float4*)(qp + c*4);
        q4[c] = make_float4(v.x*0.125f, v.y*0.125f, v.z*0.125f, v.w*0.125f);
    }
    float m, l;
    float4 o4[4];
    if (sp==0){
        const float* nk = null_kv + h*DH + ds*16;
        const float* nv = null_kv + HDH + h*DH + ds*16;
        float x0=0.f;
        #pragma unroll
        for (int c=0;c<4;c++){
            x0 += q4[c].x*nk[c*4] + q4[c].y*nk[c*4+1]
                + q4[c].z*nk[c*4+2] + q4[c].w*nk[c*4+3];
        }
        x0 += __shfl_xor_sync(0xffffffffu, x0, 1);
        x0 += __shfl_xor_sync(0xffffffffu, x0, 2);
        m=x0; l=1.f;
        #pragma unroll
        for (int c=0;c<4;c++)
            o4[c]=make_float4(nv[c*4],nv[c*4+1],nv[c*4+2],nv[c*4+3]);
    } else {
        m=-1e30f; l=0.f;
        #pragma unroll
        for (int c=0;c<4;c++) o4[c]=make_float4(0.f,0.f,0.f,0.f);
    }
    const int kc0 = sp*(KV_PER_SPLIT/64);
    for (int kc=kc0; kc<kc0 + KV_PER_SPLIT/64; kc++){
        __syncthreads();
        const float* kb = g_kvh + ((size_t)(b*NKV + kc*64))*(2*HDH) + h*(2*DH);
        #pragma unroll
        for (int j2=0;j2<4;j2++){
            ks4[qi][ds*4+j2] = *(const float4*)(kb + (size_t)qi*(2*HDH) + (ds*4+j2)*4);
            vs4[qi][ds*4+j2] = *(const float4*)(kb + (size_t)qi*(2*HDH) + DH + (ds*4+j2)*4);
        }
        __syncthreads();
        for (int j=0;j<64;j++){
            float x0=0.f,x1=0.f,x2=0.f,x3=0.f;
            #pragma unroll
            for (int cc=0;cc<4;cc++){
                float4 k4 = ks4[j][ds*4+cc];
                x0 += q4[cc].x*k4.x; x1 += q4[cc].y*k4.y;
                x2 += q4[cc].z*k4.z; x3 += q4[cc].w*k4.w;
            }
            float xv = (x0+x1)+(x2+x3);
            xv += __shfl_xor_sync(0xffffffffu, xv, 1);
            xv += __shfl_xor_sync(0xffffffffu, xv, 2);
            float mn = fmaxf(m, xv);
            float f  = __expf(m-mn);
            float e  = __expf(xv-mn);
            l = l*f + e;
            #pragma unroll
            for (int cc=0;cc<4;cc++){
                float4 v4 = vs4[j][ds*4+cc];
                o4[cc].x = o4[cc].x*f + e*v4.x;
                o4[cc].y = o4[cc].y*f + e*v4.y;
                o4[cc].z = o4[cc].z*f + e*v4.z;
                o4[cc].w = o4[cc].w*f + e*v4.w;
            }
            m = mn;
        }
    }
    const size_t base = ((size_t)((b*HEADS+h)*NSPLIT + sp))*NQ + q;
    if (ds==0){ g_pm[base] = m; g_pl[base] = l; }
    float* op = g_po + base*DH + ds*16;
    #pragma unroll
    for (int cc=0;cc<4;cc++)
        *(float4*)(op + cc*4) = o4[cc];
}

// ---------------- combine split-KV partials ----------------
__global__ __launch_bounds__(256) void k_heavy_comb(){
    const int ql = threadIdx.x >> 6, d = threadIdx.x & 63;
    const int q  = blockIdx.x*4 + ql;
    const int h  = blockIdx.y, b = blockIdx.z;
    float m[NSPLIT], l[NSPLIT];
    size_t base[NSPLIT];
    #pragma unroll
    for (int sp=0;sp<NSPLIT;sp++){
        base[sp] = ((size_t)((b*HEADS+h)*NSPLIT + sp))*NQ + q;
        m[sp] = g_pm[base[sp]];
        l[sp] = g_pl[base[sp]];
    }
    float ms = m[0];
    #pragma unroll
    for (int sp=1;sp<NSPLIT;sp++) ms = fmaxf(ms, m[sp]);
    float num=0.f, den=0.f;
    #pragma unroll
    for (int sp=0;sp<NSPLIT;sp++){
        float w = __expf(m[sp]-ms);
        den += l[sp]*w;
        num += g_po[base[sp]*DH + d]*w;
    }
    g_oh[((size_t)(b*NQ)+q)*HDH + h*DH + d] = num/den;
}

// ---------------- scatter routed output ----------------
__global__ __launch_bounds__(256) void k_scatter(const float* __restrict__ null_q,
                                                 float* __restrict__ out){
    const int j=blockIdx.x, b=blockIdx.y;
    const int n = g_sel[0][b][j];
    float* op = out + ((size_t)(b*SEQ) + n)*DIM;
    const float* rp = g_ro + ((size_t)(b*NQ) + j)*DIM;
    for (int d=threadIdx.x; d<DIM; d+=256)
        op[d] += rp[d] - null_q[d];
}

// ---------------- launch ----------------
extern "C" void kernel_launch(void* const* d_in, const int* in_sizes, int n_in,
                              void* d_out, int out_size){
    (void)in_sizes; (void)n_in; (void)out_size;
    const float* x       = (const float*)d_in[0];
    const float* ln_g    = (const float*)d_in[1];
    const float* ln_b    = (const float*)d_in[2];
    const float* w_qkv_l = (const float*)d_in[3];
    const float* w_out_l = (const float*)d_in[4];
    const float* null_q  = (const float*)d_in[5];
    const float* rt_q    = (const float*)d_in[6];
    const float* rt_kv   = (const float*)d_in[7];
    const float* rms_g   = (const float*)d_in[8];
    const float* w_q_h   = (const float*)d_in[9];
    const float* w_kv_h  = (const float*)d_in[10];
    const float* null_kv = (const float*)d_in[11];
    const float* w_out_h = (const float*)d_in[12];
    float* out = (float*)d_out;

    float *p_xn,*p_qkv,*p_lo,*p_xqn,*p_xkvn,*p_qh,*p_kvh,*p_oh,*p_ro;
    cudaGetSymbolAddress((void**)&p_xn,   g_xn);
    cudaGetSymbolAddress((void**)&p_qkv,  g_qkv);
    cudaGetSymbolAddress((void**)&p_lo,   g_lo);
    cudaGetSymbolAddress((void**)&p_xqn,  g_xqn);
    cudaGetSymbolAddress((void**)&p_xkvn, g_xkvn);
    cudaGetSymbolAddress((void**)&p_qh,   g_qh);
    cudaGetSymbolAddress((void**)&p_kvh,  g_kvh);
    cudaGetSymbolAddress((void**)&p_oh,   g_oh);
    cudaGetSymbolAddress((void**)&p_ro,   g_ro);

    // 1. layernorm + routing logits
    k_pre<<<NROWS, 256>>>(x, ln_g, ln_b, rt_q, rt_kv);
    // 2. light qkv projection (tensor cores)
    gemm_tc<<<dim3(3*HDH/128, NROWS/128), 256>>>(NROWS, 3*HDH, DIM, p_xn, w_qkv_l, p_qkv, nullptr);
    // 3. routing: fixed point + top-k set selection
    k_route<<<dim3(BATCH,2), 1024>>>();
    // 4. windowed light attention (4 lanes/query)
    k_light<<<dim3(NW, HEADS, BATCH), 256>>>();
    // 5. light output projection + null_q bias -> d_out
    gemm_tc<<<dim3(DIM/128, NROWS/128), 256>>>(NROWS, DIM, HDH, p_lo, w_out_l, out, null_q);
    // 6. gather + rmsnorm routed tokens
    k_gather<<<dim3(NQ,  BATCH), 256>>>(x, rms_g, 0);
    k_gather<<<dim3(NKV, BATCH), 256>>>(x, rms_g, 1);
    // 7. heavy projections
    gemm_tc<<<dim3(HDH/128,   BATCH*NQ/128),  256>>>(BATCH*NQ,  HDH,   DIM, p_xqn,  w_q_h,  p_qh,  nullptr);
    gemm_tc<<<dim3(2*HDH/128, BATCH*NKV/128), 256>>>(BATCH*NKV, 2*HDH, DIM, p_xkvn, w_kv_h, p_kvh, nullptr);
    // 8. heavy attention: split-KV partials (4 lanes/query) + combine
    k_heavy_part<<<dim3(NQ/64, HEADS, BATCH*NSPLIT), 256>>>(null_kv);
    k_heavy_comb<<<dim3(NQ/4, HEADS, BATCH), 256>>>();
    // 9. heavy output projection
    gemm_tc<<<dim3(DIM/128, BATCH*NQ/128), 256>>>(BATCH*NQ, DIM, HDH, p_oh, w_out_h, p_ro, nullptr);
    // 10. scatter: out[sel] += routed - null_q
    k_scatter<<<dim3(NQ, BATCH), 256>>>(null_q, out);
}

// round 8
// speedup vs baseline: 1.5854x; 1.5854x over previous
#include <cuda_runtime.h>
#include <cuda_bf16.h>
#include <stdint.h>
#include <math.h>

#define BATCH 2
#define SEQ   8192
#define DIM   1024
#define HEADS 8
#define DH    64
#define HDH   512
#define WIN   64
#define NW    (SEQ/WIN)
#define NQ    1024
#define NKV   2048
#define NROWS (BATCH*SEQ)
#define NSPLIT 4
#define KV_PER_SPLIT (NKV/NSPLIT)

// ---------------- scratch ----------------
__device__ float g_xn  [NROWS*DIM];
__device__ float g_qkv [NROWS*3*HDH];
__device__ float g_lo  [NROWS*HDH];
__device__ float g_s   [2][NROWS];
__device__ int   g_sel [2][BATCH][NKV];
__device__ float g_xqn [BATCH*NQ*DIM];
__device__ float g_xkvn[BATCH*NKV*DIM];
__device__ float g_qh  [BATCH*NQ*HDH];
__device__ float g_kvh [BATCH*NKV*2*HDH];
__device__ float g_oh  [BATCH*NQ*HDH];
__device__ float g_ro  [BATCH*NQ*DIM];
__device__ float g_pm  [BATCH*HEADS*NSPLIT*NQ];
__device__ float g_pl  [BATCH*HEADS*NSPLIT*NQ];
__device__ float g_po  [(size_t)BATCH*HEADS*NSPLIT*NQ*DH];

// ---------------- reductions ----------------
__device__ __forceinline__ float blockSum(float v){
    __shared__ float sh[33];
    int lane = threadIdx.x & 31, wid = threadIdx.x >> 5;
    #pragma unroll
    for (int o=16;o>0;o>>=1) v += __shfl_down_sync(0xffffffffu, v, o);
    __syncthreads();
    if (lane==0) sh[wid]=v;
    __syncthreads();
    if (wid==0){
        float r = (lane < (blockDim.x>>5)) ? sh[lane] : 0.f;
        #pragma unroll
        for (int o=16;o>0;o>>=1) r += __shfl_down_sync(0xffffffffu, r, o);
        if (lane==0) sh[32]=r;
    }
    __syncthreads();
    return sh[32];
}

__device__ __forceinline__ double blockSumD(double v){
    __shared__ double shd[33];
    int lane = threadIdx.x & 31, wid = threadIdx.x >> 5;
    #pragma unroll
    for (int o=16;o>0;o>>=1) v += __shfl_down_sync(0xffffffffu, v, o);
    __syncthreads();
    if (lane==0) shd[wid]=v;
    __syncthreads();
    if (wid==0){
        double r = (lane < (blockDim.x>>5)) ? shd[lane] : 0.0;
        #pragma unroll
        for (int o=16;o>0;o>>=1) r += __shfl_down_sync(0xffffffffu, r, o);
        if (lane==0) shd[32]=r;
    }
    __syncthreads();
    return shd[32];
}

// ---------------- fused layernorm + routing logits ----------------
__global__ __launch_bounds__(256) void k_pre(const float* __restrict__ x,
                                             const float* __restrict__ ln_g,
                                             const float* __restrict__ ln_b,
                                             const float* __restrict__ rt_q,
                                             const float* __restrict__ rt_kv){
    __shared__ float xr[DIM];
    size_t row = blockIdx.x;
    const float* xp = x + row*DIM;
    float s=0.f, s2=0.f, dq=0.f, dk=0.f;
    for (int d=threadIdx.x; d<DIM; d+=256){
        float v = xp[d]; xr[d]=v;
        s += v; s2 += v*v; dq += v*rt_q[d]; dk += v*rt_kv[d];
    }
    s  = blockSum(s);
    s2 = blockSum(s2);
    dq = blockSum(dq);
    dk = blockSum(dk);
    if (threadIdx.x==0){ g_s[0][row]=dq; g_s[1][row]=dk; }
    float m    = s * (1.f/DIM);
    float var  = s2 * (1.f/DIM) - m*m;
    float rstd = rsqrtf(var + 1e-5f);
    for (int d=threadIdx.x; d<DIM; d+=256)
        g_xn[row*DIM+d] = (xr[d]-m)*rstd*ln_g[d] + ln_b[d];
}

// ================= tensor-core GEMM (bf16x2 split, fp32-accurate) =========
__device__ __forceinline__ void split2(float x, float y, uint32_t& hi, uint32_t& lo){
    __nv_bfloat16 hx = __float2bfloat16_rn(x), hy = __float2bfloat16_rn(y);
    float rx = x - __bfloat162float(hx);
    float ry = y - __bfloat162float(hy);
    __nv_bfloat16 lx = __float2bfloat16_rn(rx), ly = __float2bfloat16_rn(ry);
    hi = (uint32_t)__bfloat16_as_ushort(hx) | ((uint32_t)__bfloat16_as_ushort(hy)<<16);
    lo = (uint32_t)__bfloat16_as_ushort(lx) | ((uint32_t)__bfloat16_as_ushort(ly)<<16);
}

#define LDM_X4(r0,r1,r2,r3,p) \
    asm volatile("ldmatrix.sync.aligned.m8n8.x4.shared.b16 {%0,%1,%2,%3},[%4];" \
        : "=r"(r0),"=r"(r1),"=r"(r2),"=r"(r3) : "r"(p))
#define LDM_X2T(r0,r1,p) \
    asm volatile("ldmatrix.sync.aligned.m8n8.x2.trans.shared.b16 {%0,%1},[%2];" \
        : "=r"(r0),"=r"(r1) : "r"(p))
#define MMA16816(d,a0,a1,a2,a3,b0,b1) \
    asm volatile("mma.sync.aligned.m16n8k16.row.col.f32.bf16.bf16.f32 " \
        "{%0,%1,%2,%3},{%4,%5,%6,%7},{%8,%9},{%0,%1,%2,%3};" \
        : "+f"(d[0]),"+f"(d[1]),"+f"(d[2]),"+f"(d[3]) \
        : "r"(a0),"r"(a1),"r"(a2),"r"(a3),"r"(b0),"r"(b1))

#define A_LD 24
#define B_LD 136

__global__ __launch_bounds__(256,2) void gemm_tc(int M,int N,int K,
                                                 const float* __restrict__ A,
                                                 const float* __restrict__ B,
                                                 float* __restrict__ C,
                                                 const float* __restrict__ bias){
    __shared__ __nv_bfloat16 Ah[2][128][A_LD];
    __shared__ __nv_bfloat16 Al[2][128][A_LD];
    __shared__ __nv_bfloat16 Bh[2][16][B_LD];
    __shared__ __nv_bfloat16 Bl[2][16][B_LD];
    const int tid  = threadIdx.x;
    const int lane = tid & 31, wid = tid >> 5;
    const int wm = (wid>>2)*64;
    const int wn = (wid&3)*32;
    const size_t bx = blockIdx.x, by = blockIdx.y;
    const float* Ag = A + by*128*(size_t)K;
    const float* Bg = B + bx*128;
    const int ar = tid>>1, ac = (tid&1)*8;
    const int br = tid>>4, bc = (tid&15)*8;
    const int arow  = (lane&7) + ((lane>>3)&1)*8;
    const int acolb = (lane>>4)*8;
    const int bkrow = lane & 15;

    float acc[4][4][4];
    #pragma unroll
    for (int i=0;i<4;i++)
        #pragma unroll
        for (int j=0;j<4;j++)
            #pragma unroll
            for (int c=0;c<4;c++) acc[i][j][c]=0.f;

    const int nk = K >> 4;
    float4 pa0,pa1,pb0,pb1;
    {
        const float* Ap = Ag + (size_t)ar*K + ac;
        pa0 = *(const float4*)Ap; pa1 = *(const float4*)(Ap+4);
        const float* Bp = Bg + (size_t)br*N + bc;
        pb0 = *(const float4*)Bp; pb1 = *(const float4*)(Bp+4);
    }
    for (int t=0; t<nk; t++){
        const int buf = t & 1;
        {
            uint32_t h,l;
            split2(pa0.x,pa0.y,h,l); *(uint32_t*)&Ah[buf][ar][ac+0]=h; *(uint32_t*)&Al[buf][ar][ac+0]=l;
            split2(pa0.z,pa0.w,h,l); *(uint32_t*)&Ah[buf][ar][ac+2]=h; *(uint32_t*)&Al[buf][ar][ac+2]=l;
            split2(pa1.x,pa1.y,h,l); *(uint32_t*)&Ah[buf][ar][ac+4]=h; *(uint32_t*)&Al[buf][ar][ac+4]=l;
            split2(pa1.z,pa1.w,h,l); *(uint32_t*)&Ah[buf][ar][ac+6]=h; *(uint32_t*)&Al[buf][ar][ac+6]=l;
            split2(pb0.x,pb0.y,h,l); *(uint32_t*)&Bh[buf][br][bc+0]=h; *(uint32_t*)&Bl[buf][br][bc+0]=l;
            split2(pb0.z,pb0.w,h,l); *(uint32_t*)&Bh[buf][br][bc+2]=h; *(uint32_t*)&Bl[buf][br][bc+2]=l;
            split2(pb1.x,pb1.y,h,l); *(uint32_t*)&Bh[buf][br][bc+4]=h; *(uint32_t*)&Bl[buf][br][bc+4]=l;
            split2(pb1.z,pb1.w,h,l); *(uint32_t*)&Bh[buf][br][bc+6]=h; *(uint32_t*)&Bl[buf][br][bc+6]=l;
        }
        __syncthreads();
        if (t+1 < nk){
            const float* Ap = Ag + (size_t)ar*K + (t+1)*16 + ac;
            pa0 = *(const float4*)Ap; pa1 = *(const float4*)(Ap+4);
            const float* Bp = Bg + ((size_t)((t+1)*16 + br))*N + bc;
            pb0 = *(const float4*)Bp; pb1 = *(const float4*)(Bp+4);
        }
        uint32_t bhf[4][2], blf[4][2];
        #pragma unroll
        for (int nt=0;nt<4;nt++){
            uint32_t ph = (uint32_t)__cvta_generic_to_shared(&Bh[buf][bkrow][wn+nt*8]);
            LDM_X2T(bhf[nt][0],bhf[nt][1],ph);
            uint32_t pl = (uint32_t)__cvta_generic_to_shared(&Bl[buf][bkrow][wn+nt*8]);
            LDM_X2T(blf[nt][0],blf[nt][1],pl);
        }
        #pragma unroll
        for (int mt=0;mt<4;mt++){
            uint32_t ah0,ah1,ah2,ah3, al0,al1,al2,al3;
            uint32_t pA = (uint32_t)__cvta_generic_to_shared(&Ah[buf][wm+mt*16+arow][acolb]);
            LDM_X4(ah0,ah1,ah2,ah3,pA);
            uint32_t pAl = (uint32_t)__cvta_generic_to_shared(&Al[buf][wm+mt*16+arow][acolb]);
            LDM_X4(al0,al1,al2,al3,pAl);
            #pragma unroll
            for (int nt=0;nt<4;nt++){
                MMA16816(acc[mt][nt], ah0,ah1,ah2,ah3, bhf[nt][0],bhf[nt][1]);
                MMA16816(acc[mt][nt], ah0,ah1,ah2,ah3, blf[nt][0],blf[nt][1]);
                MMA16816(acc[mt][nt], al0,al1,al2,al3, bhf[nt][0],bhf[nt][1]);
            }
        }
        __syncthreads();
    }
    const int g = lane>>2, tq = lane&3;
    #pragma unroll
    for (int nt=0;nt<4;nt++){
        const int col = (int)bx*128 + wn + nt*8 + tq*2;
        float b0=0.f,b1=0.f;
        if (bias){ b0=bias[col]; b1=bias[col+1]; }
        #pragma unroll
        for (int mt=0;mt<4;mt++){
            const int row = (int)by*128 + wm + mt*16 + g;
            float2* p0 = (float2*)(C + (size_t)row*N + col);
            *p0 = make_float2(acc[mt][nt][0]+b0, acc[mt][nt][1]+b1);
            float2* p1 = (float2*)(C + (size_t)(row+8)*N + col);
            *p1 = make_float2(acc[mt][nt][2]+b0, acc[mt][nt][3]+b1);
        }
    }
}

// ---------- light attention v3: register-tiled two-pass block attention ---
// Block = (window, head, batch). S(64x192)=Q K^T, softmax rows, O=P V.
#define LQ_QS 68
#define LQ_SS 200
#define LQ_WS 72
#define LQ_SMEM ((64*LQ_QS + 64*LQ_SS + 64*LQ_WS + 64)*4)

__global__ __launch_bounds__(256) void k_light(){
    extern __shared__ float sm[];
    float* Qs = sm;                     // [64][LQ_QS]
    float* Ss = Qs + 64*LQ_QS;          // [64][LQ_SS]
    float* Ws = Ss + 64*LQ_SS;          // [64][LQ_WS]  (K^T then V)
    float* Lr = Ws + 64*LQ_WS;          // [64] 1/l
    const int w = blockIdx.x, h = blockIdx.y, b = blockIdx.z;
    const int tid = threadIdx.x;
    const int n0 = w*WIN;
    const int tq = tid>>4, tk = tid&15;

    // load Q tile (scaled by DH^-0.5)
    for (int idx=tid; idx<64*16; idx+=256){
        int qi = idx>>4, c = idx&15;
        const float* qp = g_qkv + ((size_t)(b*SEQ + n0 + qi))*(3*HDH) + h*DH + c*4;
        float4 v = *(const float4*)qp;
        float* dst = &Qs[qi*LQ_QS + c*4];
        dst[0]=v.x*0.125f; dst[1]=v.y*0.125f; dst[2]=v.z*0.125f; dst[3]=v.w*0.125f;
    }

    // GEMM1: S = Q K^T per 64-key chunk
    for (int c=0;c<3;c++){
        const int wc = w-1+c;
        __syncthreads();
        if (wc<0 || wc>=NW){
            #pragma unroll
            for (int i=0;i<4;i++){
                float* sp = &Ss[(tq*4+i)*LQ_SS + c*64 + tk*4];
                sp[0]=-1e30f; sp[1]=-1e30f; sp[2]=-1e30f; sp[3]=-1e30f;
            }
            continue;
        }
        for (int idx=tid; idx<64*16; idx+=256){
            int key = idx&63, c4 = idx>>6;
            const float* kp = g_qkv + ((size_t)(b*SEQ + wc*WIN + key))*(3*HDH) + HDH + h*DH + c4*4;
            float4 v = *(const float4*)kp;
            Ws[(c4*4+0)*LQ_WS + key]=v.x;
            Ws[(c4*4+1)*LQ_WS + key]=v.y;
            Ws[(c4*4+2)*LQ_WS + key]=v.z;
            Ws[(c4*4+3)*LQ_WS + key]=v.w;
        }
        __syncthreads();
        float acc[4][4];
        #pragma unroll
        for (int i=0;i<4;i++){ acc[i][0]=0.f; acc[i][1]=0.f; acc[i][2]=0.f; acc[i][3]=0.f; }
        for (int d=0; d<64; d+=4){
            float4 qv[4], kv[4];
            #pragma unroll
            for (int i=0;i<4;i++) qv[i] = *(float4*)&Qs[(tq*4+i)*LQ_QS + d];
            #pragma unroll
            for (int i=0;i<4;i++) kv[i] = *(float4*)&Ws[(d+i)*LQ_WS + tk*4];
            #pragma unroll
            for (int i=0;i<4;i++){
                acc[i][0] += qv[i].x*kv[0].x + qv[i].y*kv[1].x + qv[i].z*kv[2].x + qv[i].w*kv[3].x;
                acc[i][1] += qv[i].x*kv[0].y + qv[i].y*kv[1].y + qv[i].z*kv[2].y + qv[i].w*kv[3].y;
                acc[i][2] += qv[i].x*kv[0].z + qv[i].y*kv[1].z + qv[i].z*kv[2].z + qv[i].w*kv[3].z;
                acc[i][3] += qv[i].x*kv[0].w + qv[i].y*kv[1].w + qv[i].z*kv[2].w + qv[i].w*kv[3].w;
            }
        }
        #pragma unroll
        for (int i=0;i<4;i++)
            *(float4*)&Ss[(tq*4+i)*LQ_SS + c*64 + tk*4] =
                make_float4(acc[i][0],acc[i][1],acc[i][2],acc[i][3]);
    }
    __syncthreads();

    // softmax rows: 4 threads per row, 48 keys each; P=exp(s-m) in place.
    {
        const int row = tid>>2, part = tid&3;
        float* sp = &Ss[row*LQ_SS + part*48];
        float mx = -1e30f;
        for (int k=0;k<48;k++) mx = fmaxf(mx, sp[k]);
        mx = fmaxf(mx, __shfl_xor_sync(0xffffffffu, mx, 1));
        mx = fmaxf(mx, __shfl_xor_sync(0xffffffffu, mx, 2));
        float sum=0.f;
        for (int k=0;k<48;k++){ float e = __expf(sp[k]-mx); sp[k]=e; sum+=e; }
        sum += __shfl_xor_sync(0xffffffffu, sum, 1);
        sum += __shfl_xor_sync(0xffffffffu, sum, 2);
        if (part==0) Lr[row] = 1.f/sum;
    }

    // GEMM2: O = P V per chunk
    float oacc[4][4];
    #pragma unroll
    for (int i=0;i<4;i++){ oacc[i][0]=0.f; oacc[i][1]=0.f; oacc[i][2]=0.f; oacc[i][3]=0.f; }
    for (int c=0;c<3;c++){
        const int wc = w-1+c;
        if (wc<0 || wc>=NW) continue;   // P rows are zero there
        __syncthreads();
        for (int idx=tid; idx<64*16; idx+=256){
            int key = idx&63, c4 = idx>>6;
            const float* vp = g_qkv + ((size_t)(b*SEQ + wc*WIN + key))*(3*HDH) + 2*HDH + h*DH + c4*4;
            *(float4*)&Ws[key*LQ_WS + c4*4] = *(const float4*)vp;
        }
        __syncthreads();
        for (int k=0; k<64; k+=4){
            float4 pv[4], vv[4];
            #pragma unroll
            for (int i=0;i<4;i++) pv[i] = *(float4*)&Ss[(tq*4+i)*LQ_SS + c*64 + k];
            #pragma unroll
            for (int i=0;i<4;i++) vv[i] = *(float4*)&Ws[(k+i)*LQ_WS + tk*4];
            #pragma unroll
            for (int i=0;i<4;i++){
                oacc[i][0] += pv[i].x*vv[0].x + pv[i].y*vv[1].x + pv[i].z*vv[2].x + pv[i].w*vv[3].x;
                oacc[i][1] += pv[i].x*vv[0].y + pv[i].y*vv[1].y + pv[i].z*vv[2].y + pv[i].w*vv[3].y;
                oacc[i][2] += pv[i].x*vv[0].z + pv[i].y*vv[1].z + pv[i].z*vv[2].z + pv[i].w*vv[3].z;
                oacc[i][3] += pv[i].x*vv[0].w + pv[i].y*vv[1].w + pv[i].z*vv[2].w + pv[i].w*vv[3].w;
            }
        }
    }
    // epilogue: scale by 1/l and store
    #pragma unroll
    for (int i=0;i<4;i++){
        const int q = tq*4 + i;
        float li = Lr[q];
        float* op = g_lo + ((size_t)(b*SEQ + n0 + q))*HDH + h*DH + tk*4;
        *(float4*)op = make_float4(oacc[i][0]*li, oacc[i][1]*li,
                                   oacc[i][2]*li, oacc[i][3]*li);
    }
}

// ---------------- routing: fixed point + radix top-k set selection --------
__global__ __launch_bounds__(1024) void k_route(){
    const int b = blockIdx.x, r = blockIdx.y;
    const int tid = threadIdx.x;
    const int cnt = (r==0) ? NQ : NKV;
    const float* s = g_s[r] + (size_t)b*SEQ;
    float sv[8];
    {
        float4 v0 = *(const float4*)(s + tid*8);
        float4 v1 = *(const float4*)(s + tid*8 + 4);
        sv[0]=v0.x; sv[1]=v0.y; sv[2]=v0.z; sv[3]=v0.w;
        sv[4]=v1.x; sv[5]=v1.y; sv[6]=v1.z; sv[7]=v1.w;
    }
    double E[8];
    #pragma unroll
    for (int i=0;i<8;i++) E[i] = exp((double)sv[i]);
    __shared__ double aSh;
    const double logk = (double)logf(r==0 ? 1152.0f : 2304.0f);
    double a = logk - (double)logf(8192.0f);
    for (int it=0; it<49; it++){
        double T = exp(-a);
        double tt=0.0;
        #pragma unroll
        for (int i=0;i<8;i++) tt += fmin(E[i], T);
        tt = blockSumD(tt);
        if (tid==0) aSh = logk - log(tt);
        __syncthreads();
        a = aSh;
        __syncthreads();
    }
    const float af = (float)a;
    uint32_t u[8];
    #pragma unroll
    for (int i=0;i<8;i++)
        u[i] = __float_as_uint(expf(fminf(sv[i]+af, 0.f)));
    __shared__ int hist[256];
    __shared__ uint32_t pbc; __shared__ int rbc;
    uint32_t prefix = 0; int remaining = cnt;
    for (int shift=24; shift>=0; shift-=8){
        for (int cc=tid; cc<256; cc+=1024) hist[cc]=0;
        __syncthreads();
        uint32_t pmask = (shift==24) ? 0u : (0xFFFFFFFFu << (shift+8));
        #pragma unroll
        for (int i=0;i<8;i++)
            if ((u[i] & pmask) == prefix)
                atomicAdd(&hist[(u[i]>>shift)&255], 1);
        __syncthreads();
        if (tid==0){
            int rem = remaining; uint32_t dig = 0;
            for (int d=255; d>=0; d--){
                int hv = hist[d];
                if (rem - hv <= 0){ dig = (uint32_t)d; break; }
                rem -= hv;
            }
            pbc = prefix | (dig<<shift);
            rbc = rem;
        }
        __syncthreads();
        prefix = pbc; remaining = rbc;
        __syncthreads();
    }
    const uint32_t ut = prefix;
    const int Cgt = cnt - remaining;
    __shared__ int sgt[1024], seqv[1024];
    int cgt=0, ceq=0;
    #pragma unroll
    for (int i=0;i<8;i++){
        if (u[i] > ut) cgt++;
        else if (u[i] == ut) ceq++;
    }
    sgt[tid]=cgt; seqv[tid]=ceq;
    __syncthreads();
    for (int off=1; off<1024; off<<=1){
        int a0=0,b0=0;
        if (tid>=off){ a0=sgt[tid-off]; b0=seqv[tid-off]; }
        __syncthreads();
        sgt[tid]+=a0; seqv[tid]+=b0;
        __syncthreads();
    }
    int gtPos = sgt[tid]-cgt;
    int eqPos = seqv[tid]-ceq;
    #pragma unroll
    for (int i=0;i<8;i++){
        const int idx = tid*8 + i;
        if (u[i] > ut){
            g_sel[r][b][gtPos++] = idx;
        } else if (u[i] == ut){
            int rk = eqPos++;
            if (rk < remaining) g_sel[r][b][Cgt + rk] = idx;
        }
    }
}

// ---------------- gather + rmsnorm ----------------
__global__ __launch_bounds__(256) void k_gather(const float* __restrict__ x,
                                                const float* __restrict__ rms_g,
                                                int route){
    const int j = blockIdx.x, b = blockIdx.y;
    const int cnt = route ? NKV : NQ;
    float* out = route ? g_xkvn : g_xqn;
    const int n = g_sel[route][b][j];
    const float* xp = x + ((size_t)(b*SEQ) + n)*DIM;
    float ss=0.f;
    for (int d=threadIdx.x; d<DIM; d+=256){ float v=xp[d]; ss += v*v; }
    ss = blockSum(ss);
    const float sc = 32.f / fmaxf(sqrtf(ss), 1e-12f);
    float* op = out + ((size_t)b*cnt + j)*DIM;
    for (int d=threadIdx.x; d<DIM; d+=256) op[d] = xp[d]*sc*rms_g[d];
}

// ---------------- heavy attention, split-KV partials (R6 form) ------------
__global__ __launch_bounds__(64) void k_heavy_part(const float* __restrict__ null_kv){
    const int qc = blockIdx.x, h = blockIdx.y;
    const int b  = blockIdx.z >> 2, sp = blockIdx.z & 3;
    const int t  = threadIdx.x;
    __shared__ float4 ks4[64][16];
    __shared__ float4 vs4[64][16];
    const int q = qc*64 + t;
    const float* qp = g_qh + ((size_t)(b*NQ + q))*HDH + h*DH;
    float4 q4[16];
    #pragma unroll
    for (int c=0;c<16;c++){
        float4 v = *(const float4*)(qp + c*4);
        q4[c] = make_float4(v.x*0.125f, v.y*0.125f, v.z*0.125f, v.w*0.125f);
    }
    float m, l;
    float4 o4[16];
    if (sp==0){
        const float* nk = null_kv + h*DH;
        const float* nv = null_kv + HDH + h*DH;
        float x0=0.f;
        #pragma unroll
        for (int c=0;c<16;c++){
            x0 += q4[c].x*nk[c*4] + q4[c].y*nk[c*4+1]
                + q4[c].z*nk[c*4+2] + q4[c].w*nk[c*4+3];
        }
        m=x0; l=1.f;
        #pragma unroll
        for (int c=0;c<16;c++)
            o4[c]=make_float4(nv[c*4],nv[c*4+1],nv[c*4+2],nv[c*4+3]);
    } else {
        m=-1e30f; l=0.f;
        #pragma unroll
        for (int c=0;c<16;c++) o4[c]=make_float4(0.f,0.f,0.f,0.f);
    }
    const int kc0 = sp*(KV_PER_SPLIT/64);
    for (int kc=kc0; kc<kc0 + KV_PER_SPLIT/64; kc++){
        __syncthreads();
        const float* kb = g_kvh + ((size_t)(b*NKV + kc*64))*(2*HDH) + h*(2*DH);
        #pragma unroll 4
        for (int i=0;i<64;i++){
            ((float*)&ks4[i][0])[t] = kb[(size_t)i*(2*HDH) + t];
            ((float*)&vs4[i][0])[t] = kb[(size_t)i*(2*HDH) + DH + t];
        }
        __syncthreads();
        for (int j=0;j<64;j++){
            float x0=0.f,x1=0.f,x2=0.f,x3=0.f;
            #pragma unroll
            for (int cc=0;cc<16;cc++){
                float4 k4 = ks4[j][cc];
                x0 += q4[cc].x*k4.x; x1 += q4[cc].y*k4.y;
                x2 += q4[cc].z*k4.z; x3 += q4[cc].w*k4.w;
            }
            float xv = (x0+x1)+(x2+x3);
            float mn = fmaxf(m, xv);
            float f  = __expf(m-mn);
            float e  = __expf(xv-mn);
            l = l*f + e;
            #pragma unroll
            for (int cc=0;cc<16;cc++){
                float4 v4 = vs4[j][cc];
                o4[cc].x = o4[cc].x*f + e*v4.x;
                o4[cc].y = o4[cc].y*f + e*v4.y;
                o4[cc].z = o4[cc].z*f + e*v4.z;
                o4[cc].w = o4[cc].w*f + e*v4.w;
            }
            m = mn;
        }
    }
    const size_t base = ((size_t)((b*HEADS+h)*NSPLIT + sp))*NQ + q;
    g_pm[base] = m;
    g_pl[base] = l;
    float* op = g_po + base*DH;
    #pragma unroll
    for (int cc=0;cc<16;cc++)
        *(float4*)(op + cc*4) = o4[cc];
}

// ---------------- combine split-KV partials ----------------
__global__ __launch_bounds__(256) void k_heavy_comb(){
    const int ql = threadIdx.x >> 6, d = threadIdx.x & 63;
    const int q  = blockIdx.x*4 + ql;
    const int h  = blockIdx.y, b = blockIdx.z;
    float m[NSPLIT], l[NSPLIT];
    size_t base[NSPLIT];
    #pragma unroll
    for (int sp=0;sp<NSPLIT;sp++){
        base[sp] = ((size_t)((b*HEADS+h)*NSPLIT + sp))*NQ + q;
        m[sp] = g_pm[base[sp]];
        l[sp] = g_pl[base[sp]];
    }
    float ms = m[0];
    #pragma unroll
    for (int sp=1;sp<NSPLIT;sp++) ms = fmaxf(ms, m[sp]);
    float num=0.f, den=0.f;
    #pragma unroll
    for (int sp=0;sp<NSPLIT;sp++){
        float w = __expf(m[sp]-ms);
        den += l[sp]*w;
        num += g_po[base[sp]*DH + d]*w;
    }
    g_oh[((size_t)(b*NQ)+q)*HDH + h*DH + d] = num/den;
}

// ---------------- scatter routed output ----------------
__global__ __launch_bounds__(256) void k_scatter(const float* __restrict__ null_q,
                                                 float* __restrict__ out){
    const int j=blockIdx.x, b=blockIdx.y;
    const int n = g_sel[0][b][j];
    float* op = out + ((size_t)(b*SEQ) + n)*DIM;
    const float* rp = g_ro + ((size_t)(b*NQ) + j)*DIM;
    for (int d=threadIdx.x; d<DIM; d+=256)
        op[d] += rp[d] - null_q[d];
}

// ---------------- launch ----------------
extern "C" void kernel_launch(void* const* d_in, const int* in_sizes, int n_in,
                              void* d_out, int out_size){
    (void)in_sizes; (void)n_in; (void)out_size;
    const float* x       = (const float*)d_in[0];
    const float* ln_g    = (const float*)d_in[1];
    const float* ln_b    = (const float*)d_in[2];
    const float* w_qkv_l = (const float*)d_in[3];
    const float* w_out_l = (const float*)d_in[4];
    const float* null_q  = (const float*)d_in[5];
    const float* rt_q    = (const float*)d_in[6];
    const float* rt_kv   = (const float*)d_in[7];
    const float* rms_g   = (const float*)d_in[8];
    const float* w_q_h   = (const float*)d_in[9];
    const float* w_kv_h  = (const float*)d_in[10];
    const float* null_kv = (const float*)d_in[11];
    const float* w_out_h = (const float*)d_in[12];
    float* out = (float*)d_out;

    float *p_xn,*p_qkv,*p_lo,*p_xqn,*p_xkvn,*p_qh,*p_kvh,*p_oh,*p_ro;
    cudaGetSymbolAddress((void**)&p_xn,   g_xn);
    cudaGetSymbolAddress((void**)&p_qkv,  g_qkv);
    cudaGetSymbolAddress((void**)&p_lo,   g_lo);
    cudaGetSymbolAddress((void**)&p_xqn,  g_xqn);
    cudaGetSymbolAddress((void**)&p_xkvn, g_xkvn);
    cudaGetSymbolAddress((void**)&p_qh,   g_qh);
    cudaGetSymbolAddress((void**)&p_kvh,  g_kvh);
    cudaGetSymbolAddress((void**)&p_oh,   g_oh);
    cudaGetSymbolAddress((void**)&p_ro,   g_ro);

    cudaFuncSetAttribute(k_light, cudaFuncAttributeMaxDynamicSharedMemorySize, LQ_SMEM);

    // 1. layernorm + routing logits
    k_pre<<<NROWS, 256>>>(x, ln_g, ln_b, rt_q, rt_kv);
    // 2. light qkv projection (tensor cores)
    gemm_tc<<<dim3(3*HDH/128, NROWS/128), 256>>>(NROWS, 3*HDH, DIM, p_xn, w_qkv_l, p_qkv, nullptr);
    // 3. routing: fixed point + top-k set selection
    k_route<<<dim3(BATCH,2), 1024>>>();
    // 4. windowed light attention (register-tiled block attention)
    k_light<<<dim3(NW, HEADS, BATCH), 256, LQ_SMEM>>>();
    // 5. light output projection + null_q bias -> d_out
    gemm_tc<<<dim3(DIM/128, NROWS/128), 256>>>(NROWS, DIM, HDH, p_lo, w_out_l, out, null_q);
    // 6. gather + rmsnorm routed tokens
    k_gather<<<dim3(NQ,  BATCH), 256>>>(x, rms_g, 0);
    k_gather<<<dim3(NKV, BATCH), 256>>>(x, rms_g, 1);
    // 7. heavy projections
    gemm_tc<<<dim3(HDH/128,   BATCH*NQ/128),  256>>>(BATCH*NQ,  HDH,   DIM, p_xqn,  w_q_h,  p_qh,  nullptr);
    gemm_tc<<<dim3(2*HDH/128, BATCH*NKV/128), 256>>>(BATCH*NKV, 2*HDH, DIM, p_xkvn, w_kv_h, p_kvh, nullptr);
    // 8. heavy attention: split-KV partials + combine
    k_heavy_part<<<dim3(NQ/64, HEADS, BATCH*NSPLIT), 64>>>(null_kv);
    k_heavy_comb<<<dim3(NQ/4, HEADS, BATCH), 256>>>();
    // 9. heavy output projection
    gemm_tc<<<dim3(DIM/128, BATCH*NQ/128), 256>>>(BATCH*NQ, DIM, HDH, p_oh, w_out_h, p_ro, nullptr);
    // 10. scatter: out[sel] += routed - null_q
    k_scatter<<<dim3(NQ, BATCH), 256>>>(null_q, out);
}

// round 9
// speedup vs baseline: 1.6524x; 1.0423x over previous
#include <cuda_runtime.h>
#include <cuda_bf16.h>
#include <stdint.h>
#include <math.h>

#define BATCH 2
#define SEQ   8192
#define DIM   1024
#define HEADS 8
#define DH    64
#define HDH   512
#define WIN   64
#define NW    (SEQ/WIN)
#define NQ    1024
#define NKV   2048
#define NROWS (BATCH*SEQ)
#define NSPLIT 4
#define KV_PER_SPLIT (NKV/NSPLIT)

typedef __nv_bfloat16 bf16;

// ---------------- scratch ----------------
__device__ float g_qkv [NROWS*3*HDH];
__device__ float g_s   [2][NROWS];
__device__ int   g_sel [2][BATCH][NKV];
__device__ float g_qh  [BATCH*NQ*HDH];
__device__ float g_kvh [BATCH*NKV*2*HDH];
__device__ float g_ro  [BATCH*NQ*DIM];
__device__ float g_pm  [BATCH*HEADS*NSPLIT*NQ];
__device__ float g_pl  [BATCH*HEADS*NSPLIT*NQ];
__device__ float g_po  [(size_t)BATCH*HEADS*NSPLIT*NQ*DH];
// split (hi/lo bf16) operands
__device__ bf16 g_xnh [NROWS*DIM];
__device__ bf16 g_xnl [NROWS*DIM];
__device__ bf16 g_loh [NROWS*HDH];
__device__ bf16 g_lol [NROWS*HDH];
__device__ bf16 g_xqnh[BATCH*NQ*DIM];
__device__ bf16 g_xqnl[BATCH*NQ*DIM];
__device__ bf16 g_xkvnh[BATCH*NKV*DIM];
__device__ bf16 g_xkvnl[BATCH*NKV*DIM];
__device__ bf16 g_ohh [BATCH*NQ*HDH];
__device__ bf16 g_ohl [BATCH*NQ*HDH];
__device__ bf16 g_wqkvh[DIM*3*HDH];
__device__ bf16 g_wqkvl[DIM*3*HDH];
__device__ bf16 g_wolh [HDH*DIM];
__device__ bf16 g_woll [HDH*DIM];
__device__ bf16 g_wqhh [DIM*HDH];
__device__ bf16 g_wqhl [DIM*HDH];
__device__ bf16 g_wkvhh[DIM*2*HDH];
__device__ bf16 g_wkvhl[DIM*2*HDH];
__device__ bf16 g_wohh [HDH*DIM];
__device__ bf16 g_wohl [HDH*DIM];

// ---------------- helpers ----------------
__device__ __forceinline__ void split2(float x, float y, uint32_t& hi, uint32_t& lo){
    bf16 hx = __float2bfloat16_rn(x), hy = __float2bfloat16_rn(y);
    float rx = x - __bfloat162float(hx);
    float ry = y - __bfloat162float(hy);
    bf16 lx = __float2bfloat16_rn(rx), ly = __float2bfloat16_rn(ry);
    hi = (uint32_t)__bfloat16_as_ushort(hx) | ((uint32_t)__bfloat16_as_ushort(hy)<<16);
    lo = (uint32_t)__bfloat16_as_ushort(lx) | ((uint32_t)__bfloat16_as_ushort(ly)<<16);
}
__device__ __forceinline__ void split1(float x, bf16& h, bf16& l){
    h = __float2bfloat16_rn(x);
    l = __float2bfloat16_rn(x - __bfloat162float(h));
}

__device__ __forceinline__ float blockSum(float v){
    __shared__ float sh[33];
    int lane = threadIdx.x & 31, wid = threadIdx.x >> 5;
    #pragma unroll
    for (int o=16;o>0;o>>=1) v += __shfl_down_sync(0xffffffffu, v, o);
    __syncthreads();
    if (lane==0) sh[wid]=v;
    __syncthreads();
    if (wid==0){
        float r = (lane < (blockDim.x>>5)) ? sh[lane] : 0.f;
        #pragma unroll
        for (int o=16;o>0;o>>=1) r += __shfl_down_sync(0xffffffffu, r, o);
        if (lane==0) sh[32]=r;
    }
    __syncthreads();
    return sh[32];
}

__device__ __forceinline__ double blockSumD(double v){
    __shared__ double shd[33];
    int lane = threadIdx.x & 31, wid = threadIdx.x >> 5;
    #pragma unroll
    for (int o=16;o>0;o>>=1) v += __shfl_down_sync(0xffffffffu, v, o);
    __syncthreads();
    if (lane==0) shd[wid]=v;
    __syncthreads();
    if (wid==0){
        double r = (lane < (blockDim.x>>5)) ? shd[lane] : 0.0;
        #pragma unroll
        for (int o=16;o>0;o>>=1) r += __shfl_down_sync(0xffffffffu, r, o);
        if (lane==0) shd[32]=r;
    }
    __syncthreads();
    return shd[32];
}

// ---------------- weight split conversion ----------------
__global__ __launch_bounds__(256) void k_cvtw(const float* __restrict__ W,
                                              bf16* __restrict__ Wh,
                                              bf16* __restrict__ Wl, int n4){
    int i = blockIdx.x*256 + threadIdx.x;
    if (i >= n4) return;
    float4 v = *(const float4*)(W + (size_t)i*4);
    uint32_t h0,l0,h1,l1;
    split2(v.x,v.y,h0,l0);
    split2(v.z,v.w,h1,l1);
    *(uint2*)(Wh + (size_t)i*4) = make_uint2(h0,h1);
    *(uint2*)(Wl + (size_t)i*4) = make_uint2(l0,l1);
}

// ---------------- fused layernorm + routing logits (split output) ---------
__global__ __launch_bounds__(256) void k_pre(const float* __restrict__ x,
                                             const float* __restrict__ ln_g,
                                             const float* __restrict__ ln_b,
                                             const float* __restrict__ rt_q,
                                             const float* __restrict__ rt_kv){
    __shared__ float xr[DIM];
    size_t row = blockIdx.x;
    const float* xp = x + row*DIM;
    float s=0.f, s2=0.f, dq=0.f, dk=0.f;
    for (int d=threadIdx.x; d<DIM; d+=256){
        float v = xp[d]; xr[d]=v;
        s += v; s2 += v*v; dq += v*rt_q[d]; dk += v*rt_kv[d];
    }
    s  = blockSum(s);
    s2 = blockSum(s2);
    dq = blockSum(dq);
    dk = blockSum(dk);
    if (threadIdx.x==0){ g_s[0][row]=dq; g_s[1][row]=dk; }
    float m    = s * (1.f/DIM);
    float var  = s2 * (1.f/DIM) - m*m;
    float rstd = rsqrtf(var + 1e-5f);
    for (int d=threadIdx.x; d<DIM; d+=256){
        float v = (xr[d]-m)*rstd*ln_g[d] + ln_b[d];
        bf16 h,l; split1(v,h,l);
        g_xnh[row*DIM+d]=h; g_xnl[row*DIM+d]=l;
    }
}

// ================= cp.async pipelined bf16-split tensor-core GEMM =========
#define LDM_X4(r0,r1,r2,r3,p) \
    asm volatile("ldmatrix.sync.aligned.m8n8.x4.shared.b16 {%0,%1,%2,%3},[%4];" \
        : "=r"(r0),"=r"(r1),"=r"(r2),"=r"(r3) : "r"(p))
#define LDM_X2T(r0,r1,p) \
    asm volatile("ldmatrix.sync.aligned.m8n8.x2.trans.shared.b16 {%0,%1},[%2];" \
        : "=r"(r0),"=r"(r1) : "r"(p))
#define MMA16816(d,a0,a1,a2,a3,b0,b1) \
    asm volatile("mma.sync.aligned.m16n8k16.row.col.f32.bf16.bf16.f32 " \
        "{%0,%1,%2,%3},{%4,%5,%6,%7},{%8,%9},{%0,%1,%2,%3};" \
        : "+f"(d[0]),"+f"(d[1]),"+f"(d[2]),"+f"(d[3]) \
        : "r"(a0),"r"(a1),"r"(a2),"r"(a3),"r"(b0),"r"(b1))
#define CP16(dst,src) \
    asm volatile("cp.async.ca.shared.global [%0],[%1],16;" :: "r"(dst),"l"(src))
#define CP_COMMIT asm volatile("cp.async.commit_group;")
#define CP_WAIT(n) asm volatile("cp.async.wait_group %0;" :: "n"(n))

#define A_LD 24
#define B_LD 136
#define STG 4
#define ASZ (128*A_LD)
#define BSZ (16*B_LD)
#define GEMM_SMEM ((STG*ASZ*2 + STG*BSZ*2)*2)

__global__ __launch_bounds__(256,2) void gemm_tc2(int M,int N,int K,
        const bf16* __restrict__ Ahg, const bf16* __restrict__ Alg,
        const bf16* __restrict__ Bhg, const bf16* __restrict__ Blg,
        float* __restrict__ C, const float* __restrict__ bias){
    extern __shared__ bf16 dsm[];
    bf16* Ah = dsm;
    bf16* Al = Ah + STG*ASZ;
    bf16* Bh = Al + STG*ASZ;
    bf16* Bl = Bh + STG*BSZ;
    const uint32_t sAh = (uint32_t)__cvta_generic_to_shared(Ah);
    const uint32_t sAl = (uint32_t)__cvta_generic_to_shared(Al);
    const uint32_t sBh = (uint32_t)__cvta_generic_to_shared(Bh);
    const uint32_t sBl = (uint32_t)__cvta_generic_to_shared(Bl);
    const int tid  = threadIdx.x;
    const int lane = tid & 31, wid = tid >> 5;
    const int wm = (wid>>2)*64;
    const int wn = (wid&3)*32;
    const size_t bx = blockIdx.x, by = blockIdx.y;
    const int ar = tid>>1, ac = (tid&1)*8;
    const int br = tid>>4, bc = (tid&15)*8;
    const int arow  = (lane&7) + ((lane>>3)&1)*8;
    const int acolb = (lane>>4)*8;
    const int bkrow = lane & 15;
    const bf16* aSrcH = Ahg + (by*128+ar)*(size_t)K + ac;
    const bf16* aSrcL = Alg + (by*128+ar)*(size_t)K + ac;
    const bf16* bSrcH = Bhg + (size_t)br*N + bx*128 + bc;
    const bf16* bSrcL = Blg + (size_t)br*N + bx*128 + bc;
    const uint32_t aDst = (ar*A_LD + ac)*2;
    const uint32_t bDst = (br*B_LD + bc)*2;
    const int nk = K >> 4;

    float acc[4][4][4];
    #pragma unroll
    for (int i=0;i<4;i++)
        #pragma unroll
        for (int j=0;j<4;j++)
            #pragma unroll
            for (int c=0;c<4;c++) acc[i][j][c]=0.f;

    #define ISSUE(st,kt) do{ \
        CP16(sAh + (st)*ASZ*2 + aDst, aSrcH + (kt)*16); \
        CP16(sAl + (st)*ASZ*2 + aDst, aSrcL + (kt)*16); \
        CP16(sBh + (st)*BSZ*2 + bDst, bSrcH + (size_t)(kt)*16*N); \
        CP16(sBl + (st)*BSZ*2 + bDst, bSrcL + (size_t)(kt)*16*N); \
    } while(0)

    #pragma unroll
    for (int s=0; s<STG-1; s++){
        if (s < nk) ISSUE(s, s);
        CP_COMMIT;
    }
    for (int t=0; t<nk; t++){
        CP_WAIT(STG-2);
        __syncthreads();
        const int pf = t + STG-1;
        if (pf < nk) ISSUE(pf % STG, pf);
        CP_COMMIT;
        const int st = t % STG;
        uint32_t bhf[4][2], blf[4][2];
        #pragma unroll
        for (int nt=0;nt<4;nt++){
            uint32_t ph = sBh + (st*BSZ + bkrow*B_LD + wn + nt*8)*2;
            LDM_X2T(bhf[nt][0],bhf[nt][1],ph);
            uint32_t pl = sBl + (st*BSZ + bkrow*B_LD + wn + nt*8)*2;
            LDM_X2T(blf[nt][0],blf[nt][1],pl);
        }
        #pragma unroll
        for (int mt=0;mt<4;mt++){
            uint32_t ah0,ah1,ah2,ah3, al0,al1,al2,al3;
            uint32_t pA = sAh + (st*ASZ + (wm+mt*16+arow)*A_LD + acolb)*2;
            LDM_X4(ah0,ah1,ah2,ah3,pA);
            uint32_t pAl = sAl + (st*ASZ + (wm+mt*16+arow)*A_LD + acolb)*2;
            LDM_X4(al0,al1,al2,al3,pAl);
            #pragma unroll
            for (int nt=0;nt<4;nt++){
                MMA16816(acc[mt][nt], ah0,ah1,ah2,ah3, bhf[nt][0],bhf[nt][1]);
                MMA16816(acc[mt][nt], ah0,ah1,ah2,ah3, blf[nt][0],blf[nt][1]);
                MMA16816(acc[mt][nt], al0,al1,al2,al3, bhf[nt][0],bhf[nt][1]);
            }
        }
        __syncthreads();
    }
    const int g = lane>>2, tq = lane&3;
    #pragma unroll
    for (int nt=0;nt<4;nt++){
        const int col = (int)bx*128 + wn + nt*8 + tq*2;
        float b0=0.f,b1=0.f;
        if (bias){ b0=bias[col]; b1=bias[col+1]; }
        #pragma unroll
        for (int mt=0;mt<4;mt++){
            const int row = (int)by*128 + wm + mt*16 + g;
            float2* p0 = (float2*)(C + (size_t)row*N + col);
            *p0 = make_float2(acc[mt][nt][0]+b0, acc[mt][nt][1]+b1);
            float2* p1 = (float2*)(C + (size_t)(row+8)*N + col);
            *p1 = make_float2(acc[mt][nt][2]+b0, acc[mt][nt][3]+b1);
        }
    }
}

// ---------- light attention: register-tiled two-pass block attention ------
#define LQ_QS 68
#define LQ_SS 200
#define LQ_WS 72
#define LQ_SMEM ((64*LQ_QS + 64*LQ_SS + 64*LQ_WS + 64)*4)

__global__ __launch_bounds__(256) void k_light(){
    extern __shared__ float sm[];
    float* Qs = sm;
    float* Ss = Qs + 64*LQ_QS;
    float* Ws = Ss + 64*LQ_SS;
    float* Lr = Ws + 64*LQ_WS;
    const int w = blockIdx.x, h = blockIdx.y, b = blockIdx.z;
    const int tid = threadIdx.x;
    const int n0 = w*WIN;
    const int tq = tid>>4, tk = tid&15;

    for (int idx=tid; idx<64*16; idx+=256){
        int qi = idx>>4, c = idx&15;
        const float* qp = g_qkv + ((size_t)(b*SEQ + n0 + qi))*(3*HDH) + h*DH + c*4;
        float4 v = *(const float4*)qp;
        float* dst = &Qs[qi*LQ_QS + c*4];
        dst[0]=v.x*0.125f; dst[1]=v.y*0.125f; dst[2]=v.z*0.125f; dst[3]=v.w*0.125f;
    }
    for (int c=0;c<3;c++){
        const int wc = w-1+c;
        __syncthreads();
        if (wc<0 || wc>=NW){
            #pragma unroll
            for (int i=0;i<4;i++){
                float* sp = &Ss[(tq*4+i)*LQ_SS + c*64 + tk*4];
                sp[0]=-1e30f; sp[1]=-1e30f; sp[2]=-1e30f; sp[3]=-1e30f;
            }
            continue;
        }
        for (int idx=tid; idx<64*16; idx+=256){
            int key = idx&63, c4 = idx>>6;
            const float* kp = g_qkv + ((size_t)(b*SEQ + wc*WIN + key))*(3*HDH) + HDH + h*DH + c4*4;
            float4 v = *(const float4*)kp;
            Ws[(c4*4+0)*LQ_WS + key]=v.x;
            Ws[(c4*4+1)*LQ_WS + key]=v.y;
            Ws[(c4*4+2)*LQ_WS + key]=v.z;
            Ws[(c4*4+3)*LQ_WS + key]=v.w;
        }
        __syncthreads();
        float acc[4][4];
        #pragma unroll
        for (int i=0;i<4;i++){ acc[i][0]=0.f; acc[i][1]=0.f; acc[i][2]=0.f; acc[i][3]=0.f; }
        for (int d=0; d<64; d+=4){
            float4 qv[4], kv[4];
            #pragma unroll
            for (int i=0;i<4;i++) qv[i] = *(float4*)&Qs[(tq*4+i)*LQ_QS + d];
            #pragma unroll
            for (int i=0;i<4;i++) kv[i] = *(float4*)&Ws[(d+i)*LQ_WS + tk*4];
            #pragma unroll
            for (int i=0;i<4;i++){
                acc[i][0] += qv[i].x*kv[0].x + qv[i].y*kv[1].x + qv[i].z*kv[2].x + qv[i].w*kv[3].x;
                acc[i][1] += qv[i].x*kv[0].y + qv[i].y*kv[1].y + qv[i].z*kv[2].y + qv[i].w*kv[3].y;
                acc[i][2] += qv[i].x*kv[0].z + qv[i].y*kv[1].z + qv[i].z*kv[2].z + qv[i].w*kv[3].z;
                acc[i][3] += qv[i].x*kv[0].w + qv[i].y*kv[1].w + qv[i].z*kv[2].w + qv[i].w*kv[3].w;
            }
        }
        #pragma unroll
        for (int i=0;i<4;i++)
            *(float4*)&Ss[(tq*4+i)*LQ_SS + c*64 + tk*4] =
                make_float4(acc[i][0],acc[i][1],acc[i][2],acc[i][3]);
    }
    __syncthreads();
    {
        const int row = tid>>2, part = tid&3;
        float* sp = &Ss[row*LQ_SS + part*48];
        float mx = -1e30f;
        for (int k=0;k<48;k++) mx = fmaxf(mx, sp[k]);
        mx = fmaxf(mx, __shfl_xor_sync(0xffffffffu, mx, 1));
        mx = fmaxf(mx, __shfl_xor_sync(0xffffffffu, mx, 2));
        float sum=0.f;
        for (int k=0;k<48;k++){ float e = __expf(sp[k]-mx); sp[k]=e; sum+=e; }
        sum += __shfl_xor_sync(0xffffffffu, sum, 1);
        sum += __shfl_xor_sync(0xffffffffu, sum, 2);
        if (part==0) Lr[row] = 1.f/sum;
    }
    float oacc[4][4];
    #pragma unroll
    for (int i=0;i<4;i++){ oacc[i][0]=0.f; oacc[i][1]=0.f; oacc[i][2]=0.f; oacc[i][3]=0.f; }
    for (int c=0;c<3;c++){
        const int wc = w-1+c;
        if (wc<0 || wc>=NW) continue;
        __syncthreads();
        for (int idx=tid; idx<64*16; idx+=256){
            int key = idx&63, c4 = idx>>6;
            const float* vp = g_qkv + ((size_t)(b*SEQ + wc*WIN + key))*(3*HDH) + 2*HDH + h*DH + c4*4;
            *(float4*)&Ws[key*LQ_WS + c4*4] = *(const float4*)vp;
        }
        __syncthreads();
        for (int k=0; k<64; k+=4){
            float4 pv[4], vv[4];
            #pragma unroll
            for (int i=0;i<4;i++) pv[i] = *(float4*)&Ss[(tq*4+i)*LQ_SS + c*64 + k];
            #pragma unroll
            for (int i=0;i<4;i++) vv[i] = *(float4*)&Ws[(k+i)*LQ_WS + tk*4];
            #pragma unroll
            for (int i=0;i<4;i++){
                oacc[i][0] += pv[i].x*vv[0].x + pv[i].y*vv[1].x + pv[i].z*vv[2].x + pv[i].w*vv[3].x;
                oacc[i][1] += pv[i].x*vv[0].y + pv[i].y*vv[1].y + pv[i].z*vv[2].y + pv[i].w*vv[3].y;
                oacc[i][2] += pv[i].x*vv[0].z + pv[i].y*vv[1].z + pv[i].z*vv[2].z + pv[i].w*vv[3].z;
                oacc[i][3] += pv[i].x*vv[0].w + pv[i].y*vv[1].w + pv[i].z*vv[2].w + pv[i].w*vv[3].w;
            }
        }
    }
    #pragma unroll
    for (int i=0;i<4;i++){
        const int q = tq*4 + i;
        float li = Lr[q];
        size_t off = ((size_t)(b*SEQ + n0 + q))*HDH + h*DH + tk*4;
        uint32_t h0,l0,h1,l1;
        split2(oacc[i][0]*li, oacc[i][1]*li, h0, l0);
        split2(oacc[i][2]*li, oacc[i][3]*li, h1, l1);
        *(uint2*)&g_loh[off] = make_uint2(h0,h1);
        *(uint2*)&g_lol[off] = make_uint2(l0,l1);
    }
}

// ---------------- routing: fixed point + radix top-k set selection --------
__global__ __launch_bounds__(1024) void k_route(){
    const int b = blockIdx.x, r = blockIdx.y;
    const int tid = threadIdx.x;
    const int cnt = (r==0) ? NQ : NKV;
    const float* s = g_s[r] + (size_t)b*SEQ;
    float sv[8];
    {
        float4 v0 = *(const float4*)(s + tid*8);
        float4 v1 = *(const float4*)(s + tid*8 + 4);
        sv[0]=v0.x; sv[1]=v0.y; sv[2]=v0.z; sv[3]=v0.w;
        sv[4]=v1.x; sv[5]=v1.y; sv[6]=v1.z; sv[7]=v1.w;
    }
    double E[8];
    #pragma unroll
    for (int i=0;i<8;i++) E[i] = exp((double)sv[i]);
    __shared__ double aSh;
    const double logk = (double)logf(r==0 ? 1152.0f : 2304.0f);
    double a = logk - (double)logf(8192.0f);
    for (int it=0; it<49; it++){
        double T = exp(-a);
        double tt=0.0;
        #pragma unroll
        for (int i=0;i<8;i++) tt += fmin(E[i], T);
        tt = blockSumD(tt);
        if (tid==0) aSh = logk - log(tt);
        __syncthreads();
        a = aSh;
        __syncthreads();
    }
    const float af = (float)a;
    uint32_t u[8];
    #pragma unroll
    for (int i=0;i<8;i++)
        u[i] = __float_as_uint(expf(fminf(sv[i]+af, 0.f)));
    __shared__ int hist[256];
    __shared__ uint32_t pbc; __shared__ int rbc;
    uint32_t prefix = 0; int remaining = cnt;
    for (int shift=24; shift>=0; shift-=8){
        for (int cc=tid; cc<256; cc+=1024) hist[cc]=0;
        __syncthreads();
        uint32_t pmask = (shift==24) ? 0u : (0xFFFFFFFFu << (shift+8));
        #pragma unroll
        for (int i=0;i<8;i++)
            if ((u[i] & pmask) == prefix)
                atomicAdd(&hist[(u[i]>>shift)&255], 1);
        __syncthreads();
        if (tid==0){
            int rem = remaining; uint32_t dig = 0;
            for (int d=255; d>=0; d--){
                int hv = hist[d];
                if (rem - hv <= 0){ dig = (uint32_t)d; break; }
                rem -= hv;
            }
            pbc = prefix | (dig<<shift);
            rbc = rem;
        }
        __syncthreads();
        prefix = pbc; remaining = rbc;
        __syncthreads();
    }
    const uint32_t ut = prefix;
    const int Cgt = cnt - remaining;
    __shared__ int sgt[1024], seqv[1024];
    int cgt=0, ceq=0;
    #pragma unroll
    for (int i=0;i<8;i++){
        if (u[i] > ut) cgt++;
        else if (u[i] == ut) ceq++;
    }
    sgt[tid]=cgt; seqv[tid]=ceq;
    __syncthreads();
    for (int off=1; off<1024; off<<=1){
        int a0=0,b0=0;
        if (tid>=off){ a0=sgt[tid-off]; b0=seqv[tid-off]; }
        __syncthreads();
        sgt[tid]+=a0; seqv[tid]+=b0;
        __syncthreads();
    }
    int gtPos = sgt[tid]-cgt;
    int eqPos = seqv[tid]-ceq;
    #pragma unroll
    for (int i=0;i<8;i++){
        const int idx = tid*8 + i;
        if (u[i] > ut){
            g_sel[r][b][gtPos++] = idx;
        } else if (u[i] == ut){
            int rk = eqPos++;
            if (rk < remaining) g_sel[r][b][Cgt + rk] = idx;
        }
    }
}

// ---------------- gather + rmsnorm (split output) ----------------
__global__ __launch_bounds__(256) void k_gather(const float* __restrict__ x,
                                                const float* __restrict__ rms_g,
                                                int route){
    const int j = blockIdx.x, b = blockIdx.y;
    const int cnt = route ? NKV : NQ;
    bf16* outh = route ? g_xkvnh : g_xqnh;
    bf16* outl = route ? g_xkvnl : g_xqnl;
    const int n = g_sel[route][b][j];
    const float* xp = x + ((size_t)(b*SEQ) + n)*DIM;
    float ss=0.f;
    for (int d=threadIdx.x; d<DIM; d+=256){ float v=xp[d]; ss += v*v; }
    ss = blockSum(ss);
    const float sc = 32.f / fmaxf(sqrtf(ss), 1e-12f);
    size_t base = ((size_t)b*cnt + j)*DIM;
    for (int d=threadIdx.x; d<DIM; d+=256){
        float v = xp[d]*sc*rms_g[d];
        bf16 h,l; split1(v,h,l);
        outh[base+d]=h; outl[base+d]=l;
    }
}

// ---------------- heavy attention, split-KV partials ----------------
__global__ __launch_bounds__(64) void k_heavy_part(const float* __restrict__ null_kv){
    const int qc = blockIdx.x, h = blockIdx.y;
    const int b  = blockIdx.z >> 2, sp = blockIdx.z & 3;
    const int t  = threadIdx.x;
    __shared__ float4 ks4[64][16];
    __shared__ float4 vs4[64][16];
    const int q = qc*64 + t;
    const float* qp = g_qh + ((size_t)(b*NQ + q))*HDH + h*DH;
    float4 q4[16];
    #pragma unroll
    for (int c=0;c<16;c++){
        float4 v = *(const float4*)(qp + c*4);
        q4[c] = make_float4(v.x*0.125f, v.y*0.125f, v.z*0.125f, v.w*0.125f);
    }
    float m, l;
    float4 o4[16];
    if (sp==0){
        const float* nk = null_kv + h*DH;
        const float* nv = null_kv + HDH + h*DH;
        float x0=0.f;
        #pragma unroll
        for (int c=0;c<16;c++){
            x0 += q4[c].x*nk[c*4] + q4[c].y*nk[c*4+1]
                + q4[c].z*nk[c*4+2] + q4[c].w*nk[c*4+3];
        }
        m=x0; l=1.f;
        #pragma unroll
        for (int c=0;c<16;c++)
            o4[c]=make_float4(nv[c*4],nv[c*4+1],nv[c*4+2],nv[c*4+3]);
    } else {
        m=-1e30f; l=0.f;
        #pragma unroll
        for (int c=0;c<16;c++) o4[c]=make_float4(0.f,0.f,0.f,0.f);
    }
    const int kc0 = sp*(KV_PER_SPLIT/64);
    for (int kc=kc0; kc<kc0 + KV_PER_SPLIT/64; kc++){
        __syncthreads();
        const float* kb = g_kvh + ((size_t)(b*NKV + kc*64))*(2*HDH) + h*(2*DH);
        #pragma unroll 4
        for (int i=0;i<64;i++){
            ((float*)&ks4[i][0])[t] = kb[(size_t)i*(2*HDH) + t];
            ((float*)&vs4[i][0])[t] = kb[(size_t)i*(2*HDH) + DH + t];
        }
        __syncthreads();
        for (int j=0;j<64;j++){
            float x0=0.f,x1=0.f,x2=0.f,x3=0.f;
            #pragma unroll
            for (int cc=0;cc<16;cc++){
                float4 k4 = ks4[j][cc];
                x0 += q4[cc].x*k4.x; x1 += q4[cc].y*k4.y;
                x2 += q4[cc].z*k4.z; x3 += q4[cc].w*k4.w;
            }
            float xv = (x0+x1)+(x2+x3);
            float mn = fmaxf(m, xv);
            float f  = __expf(m-mn);
            float e  = __expf(xv-mn);
            l = l*f + e;
            #pragma unroll
            for (int cc=0;cc<16;cc++){
                float4 v4 = vs4[j][cc];
                o4[cc].x = o4[cc].x*f + e*v4.x;
                o4[cc].y = o4[cc].y*f + e*v4.y;
                o4[cc].z = o4[cc].z*f + e*v4.z;
                o4[cc].w = o4[cc].w*f + e*v4.w;
            }
            m = mn;
        }
    }
    const size_t base = ((size_t)((b*HEADS+h)*NSPLIT + sp))*NQ + q;
    g_pm[base] = m;
    g_pl[base] = l;
    float* op = g_po + base*DH;
    #pragma unroll
    for (int cc=0;cc<16;cc++)
        *(float4*)(op + cc*4) = o4[cc];
}

// ---------------- combine split-KV partials (split output) ----------------
__global__ __launch_bounds__(256) void k_heavy_comb(){
    const int ql = threadIdx.x >> 6, d = threadIdx.x & 63;
    const int q  = blockIdx.x*4 + ql;
    const int h  = blockIdx.y, b = blockIdx.z;
    float m[NSPLIT], l[NSPLIT];
    size_t base[NSPLIT];
    #pragma unroll
    for (int sp=0;sp<NSPLIT;sp++){
        base[sp] = ((size_t)((b*HEADS+h)*NSPLIT + sp))*NQ + q;
        m[sp] = g_pm[base[sp]];
        l[sp] = g_pl[base[sp]];
    }
    float ms = m[0];
    #pragma unroll
    for (int sp=1;sp<NSPLIT;sp++) ms = fmaxf(ms, m[sp]);
    float num=0.f, den=0.f;
    #pragma unroll
    for (int sp=0;sp<NSPLIT;sp++){
        float w = __expf(m[sp]-ms);
        den += l[sp]*w;
        num += g_po[base[sp]*DH + d]*w;
    }
    float v = num/den;
    bf16 hh,ll; split1(v,hh,ll);
    size_t off = ((size_t)(b*NQ)+q)*HDH + h*DH + d;
    g_ohh[off]=hh; g_ohl[off]=ll;
}

// ---------------- scatter routed output ----------------
__global__ __launch_bounds__(256) void k_scatter(const float* __restrict__ null_q,
                                                 float* __restrict__ out){
    const int j=blockIdx.x, b=blockIdx.y;
    const int n = g_sel[0][b][j];
    float* op = out + ((size_t)(b*SEQ) + n)*DIM;
    const float* rp = g_ro + ((size_t)(b*NQ) + j)*DIM;
    for (int d=threadIdx.x; d<DIM; d+=256)
        op[d] += rp[d] - null_q[d];
}

// ---------------- launch ----------------
extern "C" void kernel_launch(void* const* d_in, const int* in_sizes, int n_in,
                              void* d_out, int out_size){
    (void)in_sizes; (void)n_in; (void)out_size;
    const float* x       = (const float*)d_in[0];
    const float* ln_g    = (const float*)d_in[1];
    const float* ln_b    = (const float*)d_in[2];
    const float* w_qkv_l = (const float*)d_in[3];
    const float* w_out_l = (const float*)d_in[4];
    const float* null_q  = (const float*)d_in[5];
    const float* rt_q    = (const float*)d_in[6];
    const float* rt_kv   = (const float*)d_in[7];
    const float* rms_g   = (const float*)d_in[8];
    const float* w_q_h   = (const float*)d_in[9];
    const float* w_kv_h  = (const float*)d_in[10];
    const float* null_kv = (const float*)d_in[11];
    const float* w_out_h = (const float*)d_in[12];
    float* out = (float*)d_out;

    float *p_qkv,*p_qh,*p_kvh,*p_ro;
    cudaGetSymbolAddress((void**)&p_qkv,  g_qkv);
    cudaGetSymbolAddress((void**)&p_qh,   g_qh);
    cudaGetSymbolAddress((void**)&p_kvh,  g_kvh);
    cudaGetSymbolAddress((void**)&p_ro,   g_ro);
    bf16 *p_xnh,*p_xnl,*p_loh,*p_lol,*p_xqnh,*p_xqnl,*p_xkvnh,*p_xkvnl,*p_ohh,*p_ohl;
    bf16 *p_wqkvh,*p_wqkvl,*p_wolh,*p_woll,*p_wqhh,*p_wqhl,*p_wkvhh,*p_wkvhl,*p_wohh,*p_wohl;
    cudaGetSymbolAddress((void**)&p_xnh,   g_xnh);
    cudaGetSymbolAddress((void**)&p_xnl,   g_xnl);
    cudaGetSymbolAddress((void**)&p_loh,   g_loh);
    cudaGetSymbolAddress((void**)&p_lol,   g_lol);
    cudaGetSymbolAddress((void**)&p_xqnh,  g_xqnh);
    cudaGetSymbolAddress((void**)&p_xqnl,  g_xqnl);
    cudaGetSymbolAddress((void**)&p_xkvnh, g_xkvnh);
    cudaGetSymbolAddress((void**)&p_xkvnl, g_xkvnl);
    cudaGetSymbolAddress((void**)&p_ohh,   g_ohh);
    cudaGetSymbolAddress((void**)&p_ohl,   g_ohl);
    cudaGetSymbolAddress((void**)&p_wqkvh, g_wqkvh);
    cudaGetSymbolAddress((void**)&p_wqkvl, g_wqkvl);
    cudaGetSymbolAddress((void**)&p_wolh,  g_wolh);
    cudaGetSymbolAddress((void**)&p_woll,  g_woll);
    cudaGetSymbolAddress((void**)&p_wqhh,  g_wqhh);
    cudaGetSymbolAddress((void**)&p_wqhl,  g_wqhl);
    cudaGetSymbolAddress((void**)&p_wkvhh, g_wkvhh);
    cudaGetSymbolAddress((void**)&p_wkvhl, g_wkvhl);
    cudaGetSymbolAddress((void**)&p_wohh,  g_wohh);
    cudaGetSymbolAddress((void**)&p_wohl,  g_wohl);

    cudaFuncSetAttribute(k_light,  cudaFuncAttributeMaxDynamicSharedMemorySize, LQ_SMEM);
    cudaFuncSetAttribute(gemm_tc2, cudaFuncAttributeMaxDynamicSharedMemorySize, GEMM_SMEM);

    // 0. weight splits
    k_cvtw<<<(DIM*3*HDH/4+255)/256, 256>>>(w_qkv_l, p_wqkvh, p_wqkvl, DIM*3*HDH/4);
    k_cvtw<<<(HDH*DIM/4+255)/256,  256>>>(w_out_l, p_wolh,  p_woll,  HDH*DIM/4);
    k_cvtw<<<(DIM*HDH/4+255)/256,  256>>>(w_q_h,   p_wqhh,  p_wqhl,  DIM*HDH/4);
    k_cvtw<<<(DIM*2*HDH/4+255)/256,256>>>(w_kv_h,  p_wkvhh, p_wkvhl, DIM*2*HDH/4);
    k_cvtw<<<(HDH*DIM/4+255)/256,  256>>>(w_out_h, p_wohh,  p_wohl,  HDH*DIM/4);
    // 1. layernorm + routing logits (split output)
    k_pre<<<NROWS, 256>>>(x, ln_g, ln_b, rt_q, rt_kv);
    // 2. light qkv projection
    gemm_tc2<<<dim3(3*HDH/128, NROWS/128), 256, GEMM_SMEM>>>(NROWS, 3*HDH, DIM,
        p_xnh, p_xnl, p_wqkvh, p_wqkvl, p_qkv, nullptr);
    // 3. routing
    k_route<<<dim3(BATCH,2), 1024>>>();
    // 4. windowed light attention (split output)
    k_light<<<dim3(NW, HEADS, BATCH), 256, LQ_SMEM>>>();
    // 5. light output projection + null_q bias -> d_out
    gemm_tc2<<<dim3(DIM/128, NROWS/128), 256, GEMM_SMEM>>>(NROWS, DIM, HDH,
        p_loh, p_lol, p_wolh, p_woll, out, null_q);
    // 6. gather + rmsnorm (split output)
    k_gather<<<dim3(NQ,  BATCH), 256>>>(x, rms_g, 0);
    k_gather<<<dim3(NKV, BATCH), 256>>>(x, rms_g, 1);
    // 7. heavy projections
    gemm_tc2<<<dim3(HDH/128,   BATCH*NQ/128),  256, GEMM_SMEM>>>(BATCH*NQ,  HDH,   DIM,
        p_xqnh, p_xqnl, p_wqhh, p_wqhl, p_qh, nullptr);
    gemm_tc2<<<dim3(2*HDH/128, BATCH*NKV/128), 256, GEMM_SMEM>>>(BATCH*NKV, 2*HDH, DIM,
        p_xkvnh, p_xkvnl, p_wkvhh, p_wkvhl, p_kvh, nullptr);
    // 8. heavy attention
    k_heavy_part<<<dim3(NQ/64, HEADS, BATCH*NSPLIT), 64>>>(null_kv);
    k_heavy_comb<<<dim3(NQ/4, HEADS, BATCH), 256>>>();
    // 9. heavy output projection
    gemm_tc2<<<dim3(DIM/128, BATCH*NQ/128), 256, GEMM_SMEM>>>(BATCH*NQ, DIM, HDH,
        p_ohh, p_ohl, p_wohh, p_wohl, p_ro, nullptr);
    // 10. scatter
    k_scatter<<<dim3(NQ, BATCH), 256>>>(null_q, out);
}

// round 11
// speedup vs baseline: 2.3461x; 1.4198x over previous
#include <cuda_runtime.h>
#include <cuda_fp16.h>
#include <stdint.h>
#include <math.h>

#define BATCH 2
#define SEQ   8192
#define DIM   1024
#define HEADS 8
#define DH    64
#define HDH   512
#define WIN   64
#define NW    (SEQ/WIN)
#define NQ    1024
#define NKV   2048
#define NROWS (BATCH*SEQ)
#define NSPLIT 4
#define KV_PER_SPLIT (NKV/NSPLIT)

// ---------------- scratch ----------------
__device__ float g_qkv [NROWS*3*HDH];
__device__ float g_s   [2][NROWS];
__device__ int   g_sel [2][BATCH][NKV];
__device__ float g_qh  [BATCH*NQ*HDH];
__device__ float g_kvh [BATCH*NKV*2*HDH];
__device__ float g_ro  [BATCH*NQ*DIM];
__device__ float g_pm  [BATCH*HEADS*NSPLIT*NQ];
__device__ float g_pl  [BATCH*HEADS*NSPLIT*NQ];
__device__ float g_po  [(size_t)BATCH*HEADS*NSPLIT*NQ*DH];
// fp16 operands
__device__ __half g_xnh [NROWS*DIM];
__device__ __half g_loh [NROWS*HDH];
__device__ __half g_xqnh[BATCH*NQ*DIM];
__device__ __half g_xkvnh[BATCH*NKV*DIM];
__device__ __half g_ohh [BATCH*NQ*HDH];
__device__ __half g_wqkv[DIM*3*HDH];
__device__ __half g_wol [HDH*DIM];
__device__ __half g_wqh [DIM*HDH];
__device__ __half g_wkvh[DIM*2*HDH];
__device__ __half g_woh [HDH*DIM];

// ---------------- reductions ----------------
__device__ __forceinline__ float blockSum(float v){
    __shared__ float sh[33];
    int lane = threadIdx.x & 31, wid = threadIdx.x >> 5;
    #pragma unroll
    for (int o=16;o>0;o>>=1) v += __shfl_down_sync(0xffffffffu, v, o);
    __syncthreads();
    if (lane==0) sh[wid]=v;
    __syncthreads();
    if (wid==0){
        float r = (lane < (blockDim.x>>5)) ? sh[lane] : 0.f;
        #pragma unroll
        for (int o=16;o>0;o>>=1) r += __shfl_down_sync(0xffffffffu, r, o);
        if (lane==0) sh[32]=r;
    }
    __syncthreads();
    return sh[32];
}

__device__ __forceinline__ double blockSumD(double v){
    __shared__ double shd[33];
    int lane = threadIdx.x & 31, wid = threadIdx.x >> 5;
    #pragma unroll
    for (int o=16;o>0;o>>=1) v += __shfl_down_sync(0xffffffffu, v, o);
    __syncthreads();
    if (lane==0) shd[wid]=v;
    __syncthreads();
    if (wid==0){
        double r = (lane < (blockDim.x>>5)) ? shd[lane] : 0.0;
        #pragma unroll
        for (int o=16;o>0;o>>=1) r += __shfl_down_sync(0xffffffffu, r, o);
        if (lane==0) shd[32]=r;
    }
    __syncthreads();
    return shd[32];
}

// ---------------- weight fp16 conversion ----------------
__global__ __launch_bounds__(256) void k_cvtw(const float* __restrict__ W,
                                              __half* __restrict__ Wh, int n4){
    int i = blockIdx.x*256 + threadIdx.x;
    if (i >= n4) return;
    float4 v = *(const float4*)(W + (size_t)i*4);
    *(__half2*)(Wh + (size_t)i*4)     = __floats2half2_rn(v.x, v.y);
    *(__half2*)(Wh + (size_t)i*4 + 2) = __floats2half2_rn(v.z, v.w);
}

// ---------------- fused layernorm + routing logits (fp16 output) ----------
__global__ __launch_bounds__(256) void k_pre(const float* __restrict__ x,
                                             const float* __restrict__ ln_g,
                                             const float* __restrict__ ln_b,
                                             const float* __restrict__ rt_q,
                                             const float* __restrict__ rt_kv){
    __shared__ float xr[DIM];
    size_t row = blockIdx.x;
    const float* xp = x + row*DIM;
    float s=0.f, s2=0.f, dq=0.f, dk=0.f;
    for (int d=threadIdx.x; d<DIM; d+=256){
        float v = xp[d]; xr[d]=v;
        s += v; s2 += v*v; dq += v*rt_q[d]; dk += v*rt_kv[d];
    }
    s  = blockSum(s);
    s2 = blockSum(s2);
    dq = blockSum(dq);
    dk = blockSum(dk);
    if (threadIdx.x==0){ g_s[0][row]=dq; g_s[1][row]=dk; }
    float m    = s * (1.f/DIM);
    float var  = s2 * (1.f/DIM) - m*m;
    float rstd = rsqrtf(var + 1e-5f);
    for (int d=threadIdx.x; d<DIM; d+=256){
        float v = (xr[d]-m)*rstd*ln_g[d] + ln_b[d];
        g_xnh[row*DIM+d] = __float2half_rn(v);
    }
}

// ================= cp.async pipelined fp16 tensor-core GEMM ===============
#define LDM_X4(r0,r1,r2,r3,p) \
    asm volatile("ldmatrix.sync.aligned.m8n8.x4.shared.b16 {%0,%1,%2,%3},[%4];" \
        : "=r"(r0),"=r"(r1),"=r"(r2),"=r"(r3) : "r"(p))
#define LDM_X2T(r0,r1,p) \
    asm volatile("ldmatrix.sync.aligned.m8n8.x2.trans.shared.b16 {%0,%1},[%2];" \
        : "=r"(r0),"=r"(r1) : "r"(p))
#define MMAF16(d,a0,a1,a2,a3,b0,b1) \
    asm volatile("mma.sync.aligned.m16n8k16.row.col.f32.f16.f16.f32 " \
        "{%0,%1,%2,%3},{%4,%5,%6,%7},{%8,%9},{%0,%1,%2,%3};" \
        : "+f"(d[0]),"+f"(d[1]),"+f"(d[2]),"+f"(d[3]) \
        : "r"(a0),"r"(a1),"r"(a2),"r"(a3),"r"(b0),"r"(b1))
#define CP16(dst,src) \
    asm volatile("cp.async.ca.shared.global [%0],[%1],16;" :: "r"(dst),"l"(src))
#define CP_COMMIT asm volatile("cp.async.commit_group;")
#define CP_WAIT(n) asm volatile("cp.async.wait_group %0;" :: "n"(n))

#define A_LD 24
#define B_LD 136
#define STG 4
#define ASZ (128*A_LD)
#define BSZ (16*B_LD)
#define GEMM_SMEM ((STG*ASZ + STG*BSZ)*2)

__global__ __launch_bounds__(256,2) void gemm_tc2(int M,int N,int K,
        const __half* __restrict__ Ag, const __half* __restrict__ Bg,
        float* __restrict__ C, const float* __restrict__ bias){
    extern __shared__ __half dsm[];
    __half* As = dsm;
    __half* Bs = As + STG*ASZ;
    const uint32_t sA = (uint32_t)__cvta_generic_to_shared(As);
    const uint32_t sB = (uint32_t)__cvta_generic_to_shared(Bs);
    const int tid  = threadIdx.x;
    const int lane = tid & 31, wid = tid >> 5;
    const int wm = (wid>>2)*64;
    const int wn = (wid&3)*32;
    const size_t bx = blockIdx.x, by = blockIdx.y;
    const int ar = tid>>1, ac = (tid&1)*8;
    const int br = tid>>4, bc = (tid&15)*8;
    const int arow  = (lane&7) + ((lane>>3)&1)*8;
    const int acolb = (lane>>4)*8;
    const int bkrow = lane & 15;
    const __half* aSrc = Ag + (by*128+ar)*(size_t)K + ac;
    const __half* bSrc = Bg + (size_t)br*N + bx*128 + bc;
    const uint32_t aDst = (ar*A_LD + ac)*2;
    const uint32_t bDst = (br*B_LD + bc)*2;
    const int nk = K >> 4;

    float acc[4][4][4];
    #pragma unroll
    for (int i=0;i<4;i++)
        #pragma unroll
        for (int j=0;j<4;j++)
            #pragma unroll
            for (int c=0;c<4;c++) acc[i][j][c]=0.f;

    #define ISSUE(st,kt) do{ \
        CP16(sA + (st)*ASZ*2 + aDst, aSrc + (kt)*16); \
        CP16(sB + (st)*BSZ*2 + bDst, bSrc + (size_t)(kt)*16*N); \
    } while(0)

    #pragma unroll
    for (int s=0; s<STG-1; s++){
        if (s < nk) ISSUE(s, s);
        CP_COMMIT;
    }
    for (int t=0; t<nk; t++){
        CP_WAIT(STG-2);
        __syncthreads();
        const int pf = t + STG-1;
        if (pf < nk) ISSUE(pf % STG, pf);
        CP_COMMIT;
        const int st = t % STG;
        uint32_t bf[4][2];
        #pragma unroll
        for (int nt=0;nt<4;nt++){
            uint32_t pb = sB + (st*BSZ + bkrow*B_LD + wn + nt*8)*2;
            LDM_X2T(bf[nt][0],bf[nt][1],pb);
        }
        #pragma unroll
        for (int mt=0;mt<4;mt++){
            uint32_t a0,a1,a2,a3;
            uint32_t pA = sA + (st*ASZ + (wm+mt*16+arow)*A_LD + acolb)*2;
            LDM_X4(a0,a1,a2,a3,pA);
            #pragma unroll
            for (int nt=0;nt<4;nt++)
                MMAF16(acc[mt][nt], a0,a1,a2,a3, bf[nt][0],bf[nt][1]);
        }
        __syncthreads();
    }
    const int g = lane>>2, tq = lane&3;
    #pragma unroll
    for (int nt=0;nt<4;nt++){
        const int col = (int)bx*128 + wn + nt*8 + tq*2;
        float b0=0.f,b1=0.f;
        if (bias){ b0=bias[col]; b1=bias[col+1]; }
        #pragma unroll
        for (int mt=0;mt<4;mt++){
            const int row = (int)by*128 + wm + mt*16 + g;
            float2* p0 = (float2*)(C + (size_t)row*N + col);
            *p0 = make_float2(acc[mt][nt][0]+b0, acc[mt][nt][1]+b1);
            float2* p1 = (float2*)(C + (size_t)(row+8)*N + col);
            *p1 = make_float2(acc[mt][nt][2]+b0, acc[mt][nt][3]+b1);
        }
    }
}

// ---------- light attention: register-tiled two-pass block attention ------
#define LQ_QS 68
#define LQ_SS 200
#define LQ_WS 72
#define LQ_SMEM ((64*LQ_QS + 64*LQ_SS + 64*LQ_WS + 64)*4)

__global__ __launch_bounds__(256) void k_light(){
    extern __shared__ float sm[];
    float* Qs = sm;
    float* Ss = Qs + 64*LQ_QS;
    float* Ws = Ss + 64*LQ_SS;
    float* Lr = Ws + 64*LQ_WS;
    const int w = blockIdx.x, h = blockIdx.y, b = blockIdx.z;
    const int tid = threadIdx.x;
    const int n0 = w*WIN;
    const int tq = tid>>4, tk = tid&15;

    for (int idx=tid; idx<64*16; idx+=256){
        int qi = idx>>4, c = idx&15;
        const float* qp = g_qkv + ((size_t)(b*SEQ + n0 + qi))*(3*HDH) + h*DH + c*4;
        float4 v = *(const float4*)qp;
        float* dst = &Qs[qi*LQ_QS + c*4];
        dst[0]=v.x*0.125f; dst[1]=v.y*0.125f; dst[2]=v.z*0.125f; dst[3]=v.w*0.125f;
    }
    for (int c=0;c<3;c++){
        const int wc = w-1+c;
        __syncthreads();
        if (wc<0 || wc>=NW){
            #pragma unroll
            for (int i=0;i<4;i++){
                float* sp = &Ss[(tq*4+i)*LQ_SS + c*64 + tk*4];
                sp[0]=-1e30f; sp[1]=-1e30f; sp[2]=-1e30f; sp[3]=-1e30f;
            }
            continue;
        }
        for (int idx=tid; idx<64*16; idx+=256){
            int key = idx&63, c4 = idx>>6;
            const float* kp = g_qkv + ((size_t)(b*SEQ + wc*WIN + key))*(3*HDH) + HDH + h*DH + c4*4;
            float4 v = *(const float4*)kp;
            Ws[(c4*4+0)*LQ_WS + key]=v.x;
            Ws[(c4*4+1)*LQ_WS + key]=v.y;
            Ws[(c4*4+2)*LQ_WS + key]=v.z;
            Ws[(c4*4+3)*LQ_WS + key]=v.w;
        }
        __syncthreads();
        float acc[4][4];
        #pragma unroll
        for (int i=0;i<4;i++){ acc[i][0]=0.f; acc[i][1]=0.f; acc[i][2]=0.f; acc[i][3]=0.f; }
        for (int d=0; d<64; d+=4){
            float4 qv[4], kv[4];
            #pragma unroll
            for (int i=0;i<4;i++) qv[i] = *(float4*)&Qs[(tq*4+i)*LQ_QS + d];
            #pragma unroll
            for (int i=0;i<4;i++) kv[i] = *(float4*)&Ws[(d+i)*LQ_WS + tk*4];
            #pragma unroll
            for (int i=0;i<4;i++){
                acc[i][0] += qv[i].x*kv[0].x + qv[i].y*kv[1].x + qv[i].z*kv[2].x + qv[i].w*kv[3].x;
                acc[i][1] += qv[i].x*kv[0].y + qv[i].y*kv[1].y + qv[i].z*kv[2].y + qv[i].w*kv[3].y;
                acc[i][2] += qv[i].x*kv[0].z + qv[i].y*kv[1].z + qv[i].z*kv[2].z + qv[i].w*kv[3].z;
                acc[i][3] += qv[i].x*kv[0].w + qv[i].y*kv[1].w + qv[i].z*kv[2].w + qv[i].w*kv[3].w;
            }
        }
        #pragma unroll
        for (int i=0;i<4;i++)
            *(float4*)&Ss[(tq*4+i)*LQ_SS + c*64 + tk*4] =
                make_float4(acc[i][0],acc[i][1],acc[i][2],acc[i][3]);
    }
    __syncthreads();
    {
        const int row = tid>>2, part = tid&3;
        float* sp = &Ss[row*LQ_SS + part*48];
        float mx = -1e30f;
        for (int k=0;k<48;k++) mx = fmaxf(mx, sp[k]);
        mx = fmaxf(mx, __shfl_xor_sync(0xffffffffu, mx, 1));
        mx = fmaxf(mx, __shfl_xor_sync(0xffffffffu, mx, 2));
        float sum=0.f;
        for (int k=0;k<48;k++){ float e = __expf(sp[k]-mx); sp[k]=e; sum+=e; }
        sum += __shfl_xor_sync(0xffffffffu, sum, 1);
        sum += __shfl_xor_sync(0xffffffffu, sum, 2);
        if (part==0) Lr[row] = 1.f/sum;
    }
    float oacc[4][4];
    #pragma unroll
    for (int i=0;i<4;i++){ oacc[i][0]=0.f; oacc[i][1]=0.f; oacc[i][2]=0.f; oacc[i][3]=0.f; }
    for (int c=0;c<3;c++){
        const int wc = w-1+c;
        if (wc<0 || wc>=NW) continue;
        __syncthreads();
        for (int idx=tid; idx<64*16; idx+=256){
            int key = idx&63, c4 = idx>>6;
            const float* vp = g_qkv + ((size_t)(b*SEQ + wc*WIN + key))*(3*HDH) + 2*HDH + h*DH + c4*4;
            *(float4*)&Ws[key*LQ_WS + c4*4] = *(const float4*)vp;
        }
        __syncthreads();
        for (int k=0; k<64; k+=4){
            float4 pv[4], vv[4];
            #pragma unroll
            for (int i=0;i<4;i++) pv[i] = *(float4*)&Ss[(tq*4+i)*LQ_SS + c*64 + k];
            #pragma unroll
            for (int i=0;i<4;i++) vv[i] = *(float4*)&Ws[(k+i)*LQ_WS + tk*4];
            #pragma unroll
            for (int i=0;i<4;i++){
                oacc[i][0] += pv[i].x*vv[0].x + pv[i].y*vv[1].x + pv[i].z*vv[2].x + pv[i].w*vv[3].x;
                oacc[i][1] += pv[i].x*vv[0].y + pv[i].y*vv[1].y + pv[i].z*vv[2].y + pv[i].w*vv[3].y;
                oacc[i][2] += pv[i].x*vv[0].z + pv[i].y*vv[1].z + pv[i].z*vv[2].z + pv[i].w*vv[3].z;
                oacc[i][3] += pv[i].x*vv[0].w + pv[i].y*vv[1].w + pv[i].z*vv[2].w + pv[i].w*vv[3].w;
            }
        }
    }
    #pragma unroll
    for (int i=0;i<4;i++){
        const int q = tq*4 + i;
        float li = Lr[q];
        size_t off = ((size_t)(b*SEQ + n0 + q))*HDH + h*DH + tk*4;
        *(__half2*)&g_loh[off]   = __floats2half2_rn(oacc[i][0]*li, oacc[i][1]*li);
        *(__half2*)&g_loh[off+2] = __floats2half2_rn(oacc[i][2]*li, oacc[i][3]*li);
    }
}

// ---------------- routing: fixed point + radix top-k set selection --------
__global__ __launch_bounds__(1024) void k_route(){
    const int b = blockIdx.x, r = blockIdx.y;
    const int tid = threadIdx.x;
    const int cnt = (r==0) ? NQ : NKV;
    const float* s = g_s[r] + (size_t)b*SEQ;
    float sv[8];
    {
        float4 v0 = *(const float4*)(s + tid*8);
        float4 v1 = *(const float4*)(s + tid*8 + 4);
        sv[0]=v0.x; sv[1]=v0.y; sv[2]=v0.z; sv[3]=v0.w;
        sv[4]=v1.x; sv[5]=v1.y; sv[6]=v1.z; sv[7]=v1.w;
    }
    double E[8];
    #pragma unroll
    for (int i=0;i<8;i++) E[i] = exp((double)sv[i]);
    __shared__ double aSh;
    const double logk = (double)logf(r==0 ? 1152.0f : 2304.0f);
    double a = logk - (double)logf(8192.0f);
    for (int it=0; it<49; it++){
        double T = exp(-a);
        double tt=0.0;
        #pragma unroll
        for (int i=0;i<8;i++) tt += fmin(E[i], T);
        tt = blockSumD(tt);
        if (tid==0) aSh = logk - log(tt);
        __syncthreads();
        a = aSh;
        __syncthreads();
    }
    const float af = (float)a;
    uint32_t u[8];
    #pragma unroll
    for (int i=0;i<8;i++)
        u[i] = __float_as_uint(expf(fminf(sv[i]+af, 0.f)));
    __shared__ int hist[256];
    __shared__ uint32_t pbc; __shared__ int rbc;
    uint32_t prefix = 0; int remaining = cnt;
    for (int shift=24; shift>=0; shift-=8){
        for (int cc=tid; cc<256; cc+=1024) hist[cc]=0;
        __syncthreads();
        uint32_t pmask = (shift==24) ? 0u : (0xFFFFFFFFu << (shift+8));
        #pragma unroll
        for (int i=0;i<8;i++)
            if ((u[i] & pmask) == prefix)
                atomicAdd(&hist[(u[i]>>shift)&255], 1);
        __syncthreads();
        if (tid==0){
            int rem = remaining; uint32_t dig = 0;
            for (int d=255; d>=0; d--){
                int hv = hist[d];
                if (rem - hv <= 0){ dig = (uint32_t)d; break; }
                rem -= hv;
            }
            pbc = prefix | (dig<<shift);
            rbc = rem;
        }
        __syncthreads();
        prefix = pbc; remaining = rbc;
        __syncthreads();
    }
    const uint32_t ut = prefix;
    const int Cgt = cnt - remaining;
    __shared__ int sgt[1024], seqv[1024];
    int cgt=0, ceq=0;
    #pragma unroll
    for (int i=0;i<8;i++){
        if (u[i] > ut) cgt++;
        else if (u[i] == ut) ceq++;
    }
    sgt[tid]=cgt; seqv[tid]=ceq;
    __syncthreads();
    for (int off=1; off<1024; off<<=1){
        int a0=0,b0=0;
        if (tid>=off){ a0=sgt[tid-off]; b0=seqv[tid-off]; }
        __syncthreads();
        sgt[tid]+=a0; seqv[tid]+=b0;
        __syncthreads();
    }
    int gtPos = sgt[tid]-cgt;
    int eqPos = seqv[tid]-ceq;
    #pragma unroll
    for (int i=0;i<8;i++){
        const int idx = tid*8 + i;
        if (u[i] > ut){
            g_sel[r][b][gtPos++] = idx;
        } else if (u[i] == ut){
            int rk = eqPos++;
            if (rk < remaining) g_sel[r][b][Cgt + rk] = idx;
        }
    }
}

// ---------------- gather + rmsnorm (fp16 output) ----------------
__global__ __launch_bounds__(256) void k_gather(const float* __restrict__ x,
                                                const float* __restrict__ rms_g,
                                                int route){
    const int j = blockIdx.x, b = blockIdx.y;
    const int cnt = route ? NKV : NQ;
    __half* outh = route ? g_xkvnh : g_xqnh;
    const int n = g_sel[route][b][j];
    const float* xp = x + ((size_t)(b*SEQ) + n)*DIM;
    float ss=0.f;
    for (int d=threadIdx.x; d<DIM; d+=256){ float v=xp[d]; ss += v*v; }
    ss = blockSum(ss);
    const float sc = 32.f / fmaxf(sqrtf(ss), 1e-12f);
    size_t base = ((size_t)b*cnt + j)*DIM;
    for (int d=threadIdx.x; d<DIM; d+=256)
        outh[base+d] = __float2half_rn(xp[d]*sc*rms_g[d]);
}

// ---------------- heavy attention, split-KV partials ----------------
__global__ __launch_bounds__(64) void k_heavy_part(const float* __restrict__ null_kv){
    const int qc = blockIdx.x, h = blockIdx.y;
    const int b  = blockIdx.z >> 2, sp = blockIdx.z & 3;
    const int t  = threadIdx.x;
    __shared__ float4 ks4[64][16];
    __shared__ float4 vs4[64][16];
    const int q = qc*64 + t;
    const float* qp = g_qh + ((size_t)(b*NQ + q))*HDH + h*DH;
    float4 q4[16];
    #pragma unroll
    for (int c=0;c<16;c++){
        float4 v = *(const float4*)(qp + c*4);
        q4[c] = make_float4(v.x*0.125f, v.y*0.125f, v.z*0.125f, v.w*0.125f);
    }
    float m, l;
    float4 o4[16];
    if (sp==0){
        const float* nk = null_kv + h*DH;
        const float* nv = null_kv + HDH + h*DH;
        float x0=0.f;
        #pragma unroll
        for (int c=0;c<16;c++){
            x0 += q4[c].x*nk[c*4] + q4[c].y*nk[c*4+1]
                + q4[c].z*nk[c*4+2] + q4[c].w*nk[c*4+3];
        }
        m=x0; l=1.f;
        #pragma unroll
        for (int c=0;c<16;c++)
            o4[c]=make_float4(nv[c*4],nv[c*4+1],nv[c*4+2],nv[c*4+3]);
    } else {
        m=-1e30f; l=0.f;
        #pragma unroll
        for (int c=0;c<16;c++) o4[c]=make_float4(0.f,0.f,0.f,0.f);
    }
    const int kc0 = sp*(KV_PER_SPLIT/64);
    for (int kc=kc0; kc<kc0 + KV_PER_SPLIT/64; kc++){
        __syncthreads();
        const float* kb = g_kvh + ((size_t)(b*NKV + kc*64))*(2*HDH) + h*(2*DH);
        #pragma unroll 4
        for (int i=0;i<64;i++){
            ((float*)&ks4[i][0])[t] = kb[(size_t)i*(2*HDH) + t];
            ((float*)&vs4[i][0])[t] = kb[(size_t)i*(2*HDH) + DH + t];
        }
        __syncthreads();
        for (int j=0;j<64;j++){
            float x0=0.f,x1=0.f,x2=0.f,x3=0.f;
            #pragma unroll
            for (int cc=0;cc<16;cc++){
                float4 k4 = ks4[j][cc];
                x0 += q4[cc].x*k4.x; x1 += q4[cc].y*k4.y;
                x2 += q4[cc].z*k4.z; x3 += q4[cc].w*k4.w;
            }
            float xv = (x0+x1)+(x2+x3);
            float mn = fmaxf(m, xv);
            float f  = __expf(m-mn);
            float e  = __expf(xv-mn);
            l = l*f + e;
            #pragma unroll
            for (int cc=0;cc<16;cc++){
                float4 v4 = vs4[j][cc];
                o4[cc].x = o4[cc].x*f + e*v4.x;
                o4[cc].y = o4[cc].y*f + e*v4.y;
                o4[cc].z = o4[cc].z*f + e*v4.z;
                o4[cc].w = o4[cc].w*f + e*v4.w;
            }
            m = mn;
        }
    }
    const size_t base = ((size_t)((b*HEADS+h)*NSPLIT + sp))*NQ + q;
    g_pm[base] = m;
    g_pl[base] = l;
    float* op = g_po + base*DH;
    #pragma unroll
    for (int cc=0;cc<16;cc++)
        *(float4*)(op + cc*4) = o4[cc];
}

// ---------------- combine split-KV partials (fp16 output) ----------------
__global__ __launch_bounds__(256) void k_heavy_comb(){
    const int ql = threadIdx.x >> 6, d = threadIdx.x & 63;
    const int q  = blockIdx.x*4 + ql;
    const int h  = blockIdx.y, b = blockIdx.z;
    float m[NSPLIT], l[NSPLIT];
    size_t base[NSPLIT];
    #pragma unroll
    for (int sp=0;sp<NSPLIT;sp++){
        base[sp] = ((size_t)((b*HEADS+h)*NSPLIT + sp))*NQ + q;
        m[sp] = g_pm[base[sp]];
        l[sp] = g_pl[base[sp]];
    }
    float ms = m[0];
    #pragma unroll
    for (int sp=1;sp<NSPLIT;sp++) ms = fmaxf(ms, m[sp]);
    float num=0.f, den=0.f;
    #pragma unroll
    for (int sp=0;sp<NSPLIT;sp++){
        float w = __expf(m[sp]-ms);
        den += l[sp]*w;
        num += g_po[base[sp]*DH + d]*w;
    }
    size_t off = ((size_t)(b*NQ)+q)*HDH + h*DH + d;
    g_ohh[off] = __float2half_rn(num/den);
}

// ---------------- scatter routed output ----------------
__global__ __launch_bounds__(256) void k_scatter(const float* __restrict__ null_q,
                                                 float* __restrict__ out){
    const int j=blockIdx.x, b=blockIdx.y;
    const int n = g_sel[0][b][j];
    float* op = out + ((size_t)(b*SEQ) + n)*DIM;
    const float* rp = g_ro + ((size_t)(b*NQ) + j)*DIM;
    for (int d=threadIdx.x; d<DIM; d+=256)
        op[d] += rp[d] - null_q[d];
}

// ---------------- launch ----------------
extern "C" void kernel_launch(void* const* d_in, const int* in_sizes, int n_in,
                              void* d_out, int out_size){
    (void)in_sizes; (void)n_in; (void)out_size;
    const float* x       = (const float*)d_in[0];
    const float* ln_g    = (const float*)d_in[1];
    const float* ln_b    = (const float*)d_in[2];
    const float* w_qkv_l = (const float*)d_in[3];
    const float* w_out_l = (const float*)d_in[4];
    const float* null_q  = (const float*)d_in[5];
    const float* rt_q    = (const float*)d_in[6];
    const float* rt_kv   = (const float*)d_in[7];
    const float* rms_g   = (const float*)d_in[8];
    const float* w_q_h   = (const float*)d_in[9];
    const float* w_kv_h  = (const float*)d_in[10];
    const float* null_kv = (const float*)d_in[11];
    const float* w_out_h = (const float*)d_in[12];
    float* out = (float*)d_out;

    float *p_qkv,*p_qh,*p_kvh,*p_ro;
    cudaGetSymbolAddress((void**)&p_qkv,  g_qkv);
    cudaGetSymbolAddress((void**)&p_qh,   g_qh);
    cudaGetSymbolAddress((void**)&p_kvh,  g_kvh);
    cudaGetSymbolAddress((void**)&p_ro,   g_ro);
    __half *p_xnh,*p_loh,*p_xqnh,*p_xkvnh,*p_ohh;
    __half *p_wqkv,*p_wol,*p_wqh,*p_wkvh,*p_woh;
    cudaGetSymbolAddress((void**)&p_xnh,   g_xnh);
    cudaGetSymbolAddress((void**)&p_loh,   g_loh);
    cudaGetSymbolAddress((void**)&p_xqnh,  g_xqnh);
    cudaGetSymbolAddress((void**)&p_xkvnh, g_xkvnh);
    cudaGetSymbolAddress((void**)&p_ohh,   g_ohh);
    cudaGetSymbolAddress((void**)&p_wqkv,  g_wqkv);
    cudaGetSymbolAddress((void**)&p_wol,   g_wol);
    cudaGetSymbolAddress((void**)&p_wqh,   g_wqh);
    cudaGetSymbolAddress((void**)&p_wkvh,  g_wkvh);
    cudaGetSymbolAddress((void**)&p_woh,   g_woh);

    cudaFuncSetAttribute(k_light,  cudaFuncAttributeMaxDynamicSharedMemorySize, LQ_SMEM);
    cudaFuncSetAttribute(gemm_tc2, cudaFuncAttributeMaxDynamicSharedMemorySize, GEMM_SMEM);

    // 0. weight conversions (fp16)
    k_cvtw<<<(DIM*3*HDH/4+255)/256, 256>>>(w_qkv_l, p_wqkv, DIM*3*HDH/4);
    k_cvtw<<<(HDH*DIM/4+255)/256,  256>>>(w_out_l, p_wol,  HDH*DIM/4);
    k_cvtw<<<(DIM*HDH/4+255)/256,  256>>>(w_q_h,   p_wqh,  DIM*HDH/4);
    k_cvtw<<<(DIM*2*HDH/4+255)/256,256>>>(w_kv_h,  p_wkvh, DIM*2*HDH/4);
    k_cvtw<<<(HDH*DIM/4+255)/256,  256>>>(w_out_h, p_woh,  HDH*DIM/4);
    // 1. layernorm + routing logits (fp16 output)
    k_pre<<<NROWS, 256>>>(x, ln_g, ln_b, rt_q, rt_kv);
    // 2. light qkv projection
    gemm_tc2<<<dim3(3*HDH/128, NROWS/128), 256, GEMM_SMEM>>>(NROWS, 3*HDH, DIM,
        p_xnh, p_wqkv, p_qkv, nullptr);
    // 3. routing
    k_route<<<dim3(BATCH,2), 1024>>>();
    // 4. windowed light attention (fp16 output)
    k_light<<<dim3(NW, HEADS, BATCH), 256, LQ_SMEM>>>();
    // 5. light output projection + null_q bias -> d_out
    gemm_tc2<<<dim3(DIM/128, NROWS/128), 256, GEMM_SMEM>>>(NROWS, DIM, HDH,
        p_loh, p_wol, out, null_q);
    // 6. gather + rmsnorm (fp16 output)
    k_gather<<<dim3(NQ,  BATCH), 256>>>(x, rms_g, 0);
    k_gather<<<dim3(NKV, BATCH), 256>>>(x, rms_g, 1);
    // 7. heavy projections
    gemm_tc2<<<dim3(HDH/128,   BATCH*NQ/128),  256, GEMM_SMEM>>>(BATCH*NQ,  HDH,   DIM,
        p_xqnh, p_wqh, p_qh, nullptr);
    gemm_tc2<<<dim3(2*HDH/128, BATCH*NKV/128), 256, GEMM_SMEM>>>(BATCH*NKV, 2*HDH, DIM,
        p_xkvnh, p_wkvh, p_kvh, nullptr);
    // 8. heavy attention
    k_heavy_part<<<dim3(NQ/64, HEADS, BATCH*NSPLIT), 64>>>(null_kv);
    k_heavy_comb<<<dim3(NQ/4, HEADS, BATCH), 256>>>();
    // 9. heavy output projection
    gemm_tc2<<<dim3(DIM/128, BATCH*NQ/128), 256, GEMM_SMEM>>>(BATCH*NQ, DIM, HDH,
        p_ohh, p_woh, p_ro, nullptr);
    // 10. scatter
    k_scatter<<<dim3(NQ, BATCH), 256>>>(null_q, out);
}

// round 13
// speedup vs baseline: 3.3165x; 1.4136x over previous
#include <cuda_runtime.h>
#include <cuda_fp16.h>
#include <stdint.h>
#include <math.h>

#define BATCH 2
#define SEQ   8192
#define DIM   1024
#define HEADS 8
#define DH    64
#define HDH   512
#define WIN   64
#define NW    (SEQ/WIN)
#define NQ    1024
#define NKV   2048
#define NROWS (BATCH*SEQ)
#define NSPLIT 8
#define KPS   (NKV/NSPLIT)   /* 256 keys per split */

// ---------------- scratch ----------------
__device__ float g_s   [2][NROWS];
__device__ int   g_sel [2][BATCH][NKV];
__device__ float g_ro  [BATCH*NQ*DIM];
__device__ float g_pm  [BATCH*HEADS*NSPLIT*NQ];
__device__ float g_pl  [BATCH*HEADS*NSPLIT*NQ];
__device__ float g_po  [(size_t)BATCH*HEADS*NSPLIT*NQ*DH];
// fp16 operands
__device__ __half g_xnh  [NROWS*DIM];
__device__ __half g_qkvh [NROWS*3*HDH];
__device__ __half g_loh  [NROWS*HDH];
__device__ __half g_xqnh [BATCH*NQ*DIM];
__device__ __half g_xkvnh[BATCH*NKV*DIM];
__device__ __half g_qhh  [BATCH*NQ*HDH];
__device__ __half g_kvhh [BATCH*NKV*2*HDH];
__device__ __half g_ohh  [BATCH*NQ*HDH];
__device__ __half g_wqkv [DIM*3*HDH];
__device__ __half g_wol  [HDH*DIM];
__device__ __half g_wqh  [DIM*HDH];
__device__ __half g_wkvh [DIM*2*HDH];
__device__ __half g_woh  [HDH*DIM];

// ---------------- reductions ----------------
__device__ __forceinline__ float blockSum(float v){
    __shared__ float sh[33];
    int lane = threadIdx.x & 31, wid = threadIdx.x >> 5;
    #pragma unroll
    for (int o=16;o>0;o>>=1) v += __shfl_down_sync(0xffffffffu, v, o);
    __syncthreads();
    if (lane==0) sh[wid]=v;
    __syncthreads();
    if (wid==0){
        float r = (lane < (blockDim.x>>5)) ? sh[lane] : 0.f;
        #pragma unroll
        for (int o=16;o>0;o>>=1) r += __shfl_down_sync(0xffffffffu, r, o);
        if (lane==0) sh[32]=r;
    }
    __syncthreads();
    return sh[32];
}

__device__ __forceinline__ double blockSumD(double v){
    __shared__ double shd[33];
    int lane = threadIdx.x & 31, wid = threadIdx.x >> 5;
    #pragma unroll
    for (int o=16;o>0;o>>=1) v += __shfl_down_sync(0xffffffffu, v, o);
    __syncthreads();
    if (lane==0) shd[wid]=v;
    __syncthreads();
    if (wid==0){
        double r = (lane < (blockDim.x>>5)) ? shd[lane] : 0.0;
        #pragma unroll
        for (int o=16;o>0;o>>=1) r += __shfl_down_sync(0xffffffffu, r, o);
        if (lane==0) shd[32]=r;
    }
    __syncthreads();
    return shd[32];
}

// ---------------- weight fp16 conversion ----------------
__global__ __launch_bounds__(256) void k_cvtw(const float* __restrict__ W,
                                              __half* __restrict__ Wh, int n4){
    int i = blockIdx.x*256 + threadIdx.x;
    if (i >= n4) return;
    float4 v = *(const float4*)(W + (size_t)i*4);
    *(__half2*)(Wh + (size_t)i*4)     = __floats2half2_rn(v.x, v.y);
    *(__half2*)(Wh + (size_t)i*4 + 2) = __floats2half2_rn(v.z, v.w);
}

// ---------------- fused layernorm + routing logits (fp16 output) ----------
__global__ __launch_bounds__(256) void k_pre(const float* __restrict__ x,
                                             const float* __restrict__ ln_g,
                                             const float* __restrict__ ln_b,
                                             const float* __restrict__ rt_q,
                                             const float* __restrict__ rt_kv){
    __shared__ float xr[DIM];
    size_t row = blockIdx.x;
    const float* xp = x + row*DIM;
    float s=0.f, s2=0.f, dq=0.f, dk=0.f;
    for (int d=threadIdx.x; d<DIM; d+=256){
        float v = xp[d]; xr[d]=v;
        s += v; s2 += v*v; dq += v*rt_q[d]; dk += v*rt_kv[d];
    }
    s  = blockSum(s);
    s2 = blockSum(s2);
    dq = blockSum(dq);
    dk = blockSum(dk);
    if (threadIdx.x==0){ g_s[0][row]=dq; g_s[1][row]=dk; }
    float m    = s * (1.f/DIM);
    float var  = s2 * (1.f/DIM) - m*m;
    float rstd = rsqrtf(var + 1e-5f);
    for (int d=threadIdx.x; d<DIM; d+=256){
        float v = (xr[d]-m)*rstd*ln_g[d] + ln_b[d];
        g_xnh[row*DIM+d] = __float2half_rn(v);
    }
}

// ================= cp.async pipelined fp16 tensor-core GEMM ===============
#define LDM_X4(r0,r1,r2,r3,p) \
    asm volatile("ldmatrix.sync.aligned.m8n8.x4.shared.b16 {%0,%1,%2,%3},[%4];" \
        : "=r"(r0),"=r"(r1),"=r"(r2),"=r"(r3) : "r"(p))
#define LDM_X2T(r0,r1,p) \
    asm volatile("ldmatrix.sync.aligned.m8n8.x2.trans.shared.b16 {%0,%1},[%2];" \
        : "=r"(r0),"=r"(r1) : "r"(p))
#define MMAF16(d,a0,a1,a2,a3,b0,b1) \
    asm volatile("mma.sync.aligned.m16n8k16.row.col.f32.f16.f16.f32 " \
        "{%0,%1,%2,%3},{%4,%5,%6,%7},{%8,%9},{%0,%1,%2,%3};" \
        : "+f"(d[0]),"+f"(d[1]),"+f"(d[2]),"+f"(d[3]) \
        : "r"(a0),"r"(a1),"r"(a2),"r"(a3),"r"(b0),"r"(b1))
#define CP16(dst,src) \
    asm volatile("cp.async.ca.shared.global [%0],[%1],16;" :: "r"(dst),"l"(src))
#define CP_COMMIT asm volatile("cp.async.commit_group;")
#define CP_WAIT(n) asm volatile("cp.async.wait_group %0;" :: "n"(n))

#define A_LD 24
#define B_LD 136
#define STG 4
#define ASZ (128*A_LD)
#define BSZ (16*B_LD)
#define GEMM_SMEM ((STG*ASZ + STG*BSZ)*2)

__global__ __launch_bounds__(256,2) void gemm_tc2(int M,int N,int K,
        const __half* __restrict__ Ag, const __half* __restrict__ Bg,
        float* __restrict__ C, __half* __restrict__ Ch,
        const float* __restrict__ bias){
    extern __shared__ __half dsm[];
    __half* As = dsm;
    __half* Bs = As + STG*ASZ;
    const uint32_t sA = (uint32_t)__cvta_generic_to_shared(As);
    const uint32_t sB = (uint32_t)__cvta_generic_to_shared(Bs);
    const int tid  = threadIdx.x;
    const int lane = tid & 31, wid = tid >> 5;
    const int wm = (wid>>2)*64;
    const int wn = (wid&3)*32;
    const size_t bx = blockIdx.x, by = blockIdx.y;
    const int ar = tid>>1, ac = (tid&1)*8;
    const int br = tid>>4, bc = (tid&15)*8;
    const int arow  = (lane&7) + ((lane>>3)&1)*8;
    const int acolb = (lane>>4)*8;
    const int bkrow = lane & 15;
    const __half* aSrc = Ag + (by*128+ar)*(size_t)K + ac;
    const __half* bSrc = Bg + (size_t)br*N + bx*128 + bc;
    const uint32_t aDst = (ar*A_LD + ac)*2;
    const uint32_t bDst = (br*B_LD + bc)*2;
    const int nk = K >> 4;

    float acc[4][4][4];
    #pragma unroll
    for (int i=0;i<4;i++)
        #pragma unroll
        for (int j=0;j<4;j++)
            #pragma unroll
            for (int c=0;c<4;c++) acc[i][j][c]=0.f;

    #define ISSUE(st,kt) do{ \
        CP16(sA + (st)*ASZ*2 + aDst, aSrc + (kt)*16); \
        CP16(sB + (st)*BSZ*2 + bDst, bSrc + (size_t)(kt)*16*N); \
    } while(0)

    #pragma unroll
    for (int s=0; s<STG-1; s++){
        if (s < nk) ISSUE(s, s);
        CP_COMMIT;
    }
    for (int t=0; t<nk; t++){
        CP_WAIT(STG-2);
        __syncthreads();
        const int pf = t + STG-1;
        if (pf < nk) ISSUE(pf % STG, pf);
        CP_COMMIT;
        const int st = t % STG;
        uint32_t bf[4][2];
        #pragma unroll
        for (int nt=0;nt<4;nt++){
            uint32_t pb = sB + (st*BSZ + bkrow*B_LD + wn + nt*8)*2;
            LDM_X2T(bf[nt][0],bf[nt][1],pb);
        }
        #pragma unroll
        for (int mt=0;mt<4;mt++){
            uint32_t a0,a1,a2,a3;
            uint32_t pA = sA + (st*ASZ + (wm+mt*16+arow)*A_LD + acolb)*2;
            LDM_X4(a0,a1,a2,a3,pA);
            #pragma unroll
            for (int nt=0;nt<4;nt++)
                MMAF16(acc[mt][nt], a0,a1,a2,a3, bf[nt][0],bf[nt][1]);
        }
        __syncthreads();
    }
    const int g = lane>>2, tq = lane&3;
    #pragma unroll
    for (int nt=0;nt<4;nt++){
        const int col = (int)bx*128 + wn + nt*8 + tq*2;
        float b0=0.f,b1=0.f;
        if (bias){ b0=bias[col]; b1=bias[col+1]; }
        #pragma unroll
        for (int mt=0;mt<4;mt++){
            const int row = (int)by*128 + wm + mt*16 + g;
            if (Ch){
                *(__half2*)(Ch + (size_t)row*N + col) =
                    __floats2half2_rn(acc[mt][nt][0], acc[mt][nt][1]);
                *(__half2*)(Ch + (size_t)(row+8)*N + col) =
                    __floats2half2_rn(acc[mt][nt][2], acc[mt][nt][3]);
            } else {
                *(float2*)(C + (size_t)row*N + col) =
                    make_float2(acc[mt][nt][0]+b0, acc[mt][nt][1]+b1);
                *(float2*)(C + (size_t)(row+8)*N + col) =
                    make_float2(acc[mt][nt][2]+b0, acc[mt][nt][3]+b1);
            }
        }
    }
}

// ---------- light attention v4: fp16 MMA block attention ------------------
// Block (w,h,b), 256 thr / 8 warps. S=Q K^T (MMA) -> softmax -> O=P V (MMA).
#define LQS 72
#define LPS 200
#define LQ_SMEM ((64*LQS + 64*LQS + 64*LPS)*2 + (64*LPS + 64)*4)

__global__ __launch_bounds__(256) void k_light(){
    extern __shared__ char smraw[];
    __half* Qh = (__half*)smraw;            // [64][LQS]
    __half* Wh = Qh + 64*LQS;               // [64][LQS] K^T then V
    __half* Ph = Wh + 64*LQS;               // [64][LPS]
    float*  Ss = (float*)(Ph + 64*LPS);     // [64][LPS]
    float*  Lr = Ss + 64*LPS;               // [64]
    const int w = blockIdx.x, h = blockIdx.y, b = blockIdx.z;
    const int tid = threadIdx.x;
    const int lane = tid & 31, wid = tid >> 5;
    const int n0 = w*WIN;
    const int mt = wid>>1, nh = (wid&1)*32;
    const int g = lane>>2, tq = lane&3;
    const int arow  = (lane&7) + ((lane>>3)&1)*8;
    const int acolb = (lane>>4)*8;
    const int bkrow = lane & 15;

    // load Q (fp16, unscaled)
    for (int idx=tid; idx<64*8; idx+=256){
        int r=idx>>3, s8=idx&7;
        *(uint4*)&Qh[r*LQS+s8*8] =
            *(const uint4*)&g_qkvh[((size_t)(b*SEQ+n0+r))*(3*HDH)+h*DH+s8*8];
    }
    // S chunks
    for (int c=0;c<3;c++){
        const int wc = w-1+c;
        __syncthreads();
        if (wc<0 || wc>=NW){
            for (int idx=tid; idx<4096; idx+=256){
                int r=idx>>6, k=idx&63;
                Ss[r*LPS + c*64 + k] = -1e30f;
            }
            continue;
        }
        // K^T into Wh[dim][key]
        for (int idx=tid; idx<64*32; idx+=256){
            int key=idx&63, d2=idx>>6;
            __half2 v = *(const __half2*)&g_qkvh[((size_t)(b*SEQ+wc*WIN+key))*(3*HDH)+HDH+h*DH+d2*2];
            Wh[(d2*2)*LQS + key]   = __low2half(v);
            Wh[(d2*2+1)*LQS + key] = __high2half(v);
        }
        __syncthreads();
        float sacc[4][4];
        #pragma unroll
        for (int nt=0;nt<4;nt++){ sacc[nt][0]=0;sacc[nt][1]=0;sacc[nt][2]=0;sacc[nt][3]=0; }
        #pragma unroll
        for (int ks=0;ks<4;ks++){
            uint32_t a0,a1,a2,a3;
            uint32_t pA = (uint32_t)__cvta_generic_to_shared(&Qh[(mt*16+arow)*LQS + ks*16 + acolb]);
            LDM_X4(a0,a1,a2,a3,pA);
            #pragma unroll
            for (int nt=0;nt<4;nt++){
                uint32_t b0,b1;
                uint32_t pB = (uint32_t)__cvta_generic_to_shared(&Wh[(ks*16+bkrow)*LQS + nh + nt*8]);
                LDM_X2T(b0,b1,pB);
                MMAF16(sacc[nt], a0,a1,a2,a3, b0,b1);
            }
        }
        #pragma unroll
        for (int nt=0;nt<4;nt++){
            int col = c*64 + nh + nt*8 + tq*2;
            *(float2*)&Ss[(mt*16+g)*LPS + col]   = make_float2(sacc[nt][0]*0.125f, sacc[nt][1]*0.125f);
            *(float2*)&Ss[(mt*16+g+8)*LPS + col] = make_float2(sacc[nt][2]*0.125f, sacc[nt][3]*0.125f);
        }
    }
    __syncthreads();
    // softmax (192 keys, 4 thr/row), P fp16
    {
        const int row = tid>>2, part = tid&3;
        float* sp = &Ss[row*LPS + part*48];
        __half* pp = &Ph[row*LPS + part*48];
        float mx = -1e30f;
        for (int k=0;k<48;k++) mx = fmaxf(mx, sp[k]);
        mx = fmaxf(mx, __shfl_xor_sync(0xffffffffu, mx, 1));
        mx = fmaxf(mx, __shfl_xor_sync(0xffffffffu, mx, 2));
        float sum=0.f;
        for (int k=0;k<48;k++){ float e=__expf(sp[k]-mx); pp[k]=__float2half_rn(e); sum+=e; }
        sum += __shfl_xor_sync(0xffffffffu, sum, 1);
        sum += __shfl_xor_sync(0xffffffffu, sum, 2);
        if (part==0) Lr[row] = 1.f/sum;
    }
    // O = P V
    float oacc[4][4];
    #pragma unroll
    for (int nt=0;nt<4;nt++){ oacc[nt][0]=0;oacc[nt][1]=0;oacc[nt][2]=0;oacc[nt][3]=0; }
    for (int c=0;c<3;c++){
        const int wc = w-1+c;
        if (wc<0 || wc>=NW) continue;
        __syncthreads();
        for (int idx=tid; idx<64*8; idx+=256){
            int key=idx>>3, s8=idx&7;
            *(uint4*)&Wh[key*LQS+s8*8] =
                *(const uint4*)&g_qkvh[((size_t)(b*SEQ+wc*WIN+key))*(3*HDH)+2*HDH+h*DH+s8*8];
        }
        __syncthreads();
        #pragma unroll
        for (int ksl=0;ksl<4;ksl++){
            uint32_t a0,a1,a2,a3;
            uint32_t pA = (uint32_t)__cvta_generic_to_shared(&Ph[(mt*16+arow)*LPS + (c*4+ksl)*16 + acolb]);
            LDM_X4(a0,a1,a2,a3,pA);
            #pragma unroll
            for (int nt=0;nt<4;nt++){
                uint32_t b0,b1;
                uint32_t pB = (uint32_t)__cvta_generic_to_shared(&Wh[(ksl*16+bkrow)*LQS + nh + nt*8]);
                LDM_X2T(b0,b1,pB);
                MMAF16(oacc[nt], a0,a1,a2,a3, b0,b1);
            }
        }
    }
    __syncthreads();
    {
        float li0 = Lr[mt*16+g], li1 = Lr[mt*16+g+8];
        #pragma unroll
        for (int nt=0;nt<4;nt++){
            int col = nh + nt*8 + tq*2;
            size_t o0 = ((size_t)(b*SEQ+n0+mt*16+g))*HDH + h*DH + col;
            size_t o1 = ((size_t)(b*SEQ+n0+mt*16+g+8))*HDH + h*DH + col;
            *(__half2*)&g_loh[o0] = __floats2half2_rn(oacc[nt][0]*li0, oacc[nt][1]*li0);
            *(__half2*)&g_loh[o1] = __floats2half2_rn(oacc[nt][2]*li1, oacc[nt][3]*li1);
        }
    }
}

// ---------- heavy attention v2: fp16 MMA split-KV partials ---------------
#define HPS 264
#define HV_SMEM ((64*LQS + 64*LQS + 64*HPS)*2 + (64*HPS + 128)*4)

__global__ __launch_bounds__(256) void k_heavy_part(){
    extern __shared__ char smraw[];
    __half* Qh = (__half*)smraw;            // [64][LQS]
    __half* Wh = Qh + 64*LQS;               // [64][LQS]
    __half* Ph = Wh + 64*LQS;               // [64][HPS]
    float*  Ss = (float*)(Ph + 64*HPS);     // [64][HPS]
    float*  Mr = Ss + 64*HPS;               // [64]
    float*  Lr = Mr + 64;                   // [64]
    const int qc = blockIdx.x, h = blockIdx.y;
    const int b  = blockIdx.z >> 3, sp = blockIdx.z & 7;
    const int tid = threadIdx.x;
    const int lane = tid & 31, wid = tid >> 5;
    const int mt = wid>>1, nh = (wid&1)*32;
    const int g = lane>>2, tq = lane&3;
    const int arow  = (lane&7) + ((lane>>3)&1)*8;
    const int acolb = (lane>>4)*8;
    const int bkrow = lane & 15;
    const int key0 = sp*KPS;

    for (int idx=tid; idx<64*8; idx+=256){
        int r=idx>>3, s8=idx&7;
        *(uint4*)&Qh[r*LQS+s8*8] =
            *(const uint4*)&g_qhh[((size_t)(b*NQ+qc*64+r))*HDH + h*DH + s8*8];
    }
    for (int c=0;c<4;c++){
        __syncthreads();
        for (int idx=tid; idx<64*32; idx+=256){
            int key=idx&63, d2=idx>>6;
            __half2 v = *(const __half2*)&g_kvhh[((size_t)(b*NKV+key0+c*64+key))*(2*HDH)+h*(2*DH)+d2*2];
            Wh[(d2*2)*LQS + key]   = __low2half(v);
            Wh[(d2*2+1)*LQS + key] = __high2half(v);
        }
        __syncthreads();
        float sacc[4][4];
        #pragma unroll
        for (int nt=0;nt<4;nt++){ sacc[nt][0]=0;sacc[nt][1]=0;sacc[nt][2]=0;sacc[nt][3]=0; }
        #pragma unroll
        for (int ks=0;ks<4;ks++){
            uint32_t a0,a1,a2,a3;
            uint32_t pA = (uint32_t)__cvta_generic_to_shared(&Qh[(mt*16+arow)*LQS + ks*16 + acolb]);
            LDM_X4(a0,a1,a2,a3,pA);
            #pragma unroll
            for (int nt=0;nt<4;nt++){
                uint32_t b0,b1;
                uint32_t pB = (uint32_t)__cvta_generic_to_shared(&Wh[(ks*16+bkrow)*LQS + nh + nt*8]);
                LDM_X2T(b0,b1,pB);
                MMAF16(sacc[nt], a0,a1,a2,a3, b0,b1);
            }
        }
        #pragma unroll
        for (int nt=0;nt<4;nt++){
            int col = c*64 + nh + nt*8 + tq*2;
            *(float2*)&Ss[(mt*16+g)*HPS + col]   = make_float2(sacc[nt][0]*0.125f, sacc[nt][1]*0.125f);
            *(float2*)&Ss[(mt*16+g+8)*HPS + col] = make_float2(sacc[nt][2]*0.125f, sacc[nt][3]*0.125f);
        }
    }
    __syncthreads();
    // softmax over 256 keys (4 thr/row, 64 each), unnormalized P
    {
        const int row = tid>>2, part = tid&3;
        float* spt = &Ss[row*HPS + part*64];
        __half* pp = &Ph[row*HPS + part*64];
        float mx = -1e30f;
        for (int k=0;k<64;k++) mx = fmaxf(mx, spt[k]);
        mx = fmaxf(mx, __shfl_xor_sync(0xffffffffu, mx, 1));
        mx = fmaxf(mx, __shfl_xor_sync(0xffffffffu, mx, 2));
        float sum=0.f;
        for (int k=0;k<64;k++){ float e=__expf(spt[k]-mx); pp[k]=__float2half_rn(e); sum+=e; }
        sum += __shfl_xor_sync(0xffffffffu, sum, 1);
        sum += __shfl_xor_sync(0xffffffffu, sum, 2);
        if (part==0){ Mr[row]=mx; Lr[row]=sum; }
    }
    // O = P V (unnormalized)
    float oacc[4][4];
    #pragma unroll
    for (int nt=0;nt<4;nt++){ oacc[nt][0]=0;oacc[nt][1]=0;oacc[nt][2]=0;oacc[nt][3]=0; }
    for (int c=0;c<4;c++){
        __syncthreads();
        for (int idx=tid; idx<64*8; idx+=256){
            int key=idx>>3, s8=idx&7;
            *(uint4*)&Wh[key*LQS+s8*8] =
                *(const uint4*)&g_kvhh[((size_t)(b*NKV+key0+c*64+key))*(2*HDH)+h*(2*DH)+DH+s8*8];
        }
        __syncthreads();
        #pragma unroll
        for (int ksl=0;ksl<4;ksl++){
            uint32_t a0,a1,a2,a3;
            uint32_t pA = (uint32_t)__cvta_generic_to_shared(&Ph[(mt*16+arow)*HPS + (c*4+ksl)*16 + acolb]);
            LDM_X4(a0,a1,a2,a3,pA);
            #pragma unroll
            for (int nt=0;nt<4;nt++){
                uint32_t b0,b1;
                uint32_t pB = (uint32_t)__cvta_generic_to_shared(&Wh[(ksl*16+bkrow)*LQS + nh + nt*8]);
                LDM_X2T(b0,b1,pB);
                MMAF16(oacc[nt], a0,a1,a2,a3, b0,b1);
            }
        }
    }
    __syncthreads();
    {
        const size_t pbase = ((size_t)((b*HEADS+h)*NSPLIT + sp))*NQ + qc*64;
        if (tid < 64){ g_pm[pbase+tid]=Mr[tid]; g_pl[pbase+tid]=Lr[tid]; }
        #pragma unroll
        for (int nt=0;nt<4;nt++){
            int col = nh + nt*8 + tq*2;
            *(float2*)&g_po[(pbase+mt*16+g)*DH + col]   = make_float2(oacc[nt][0], oacc[nt][1]);
            *(float2*)&g_po[(pbase+mt*16+g+8)*DH + col] = make_float2(oacc[nt][2], oacc[nt][3]);
        }
    }
}

// ---------------- combine split-KV partials + null kv ----------------
__global__ __launch_bounds__(256) void k_heavy_comb(const float* __restrict__ null_kv){
    const int ql = threadIdx.x >> 6, d = threadIdx.x & 63;
    const int q  = blockIdx.x*4 + ql;
    const int h  = blockIdx.y, b = blockIdx.z;
    __shared__ float red[8];
    float qd = __half2float(g_qhh[((size_t)(b*NQ+q))*HDH + h*DH + d]);
    float p = qd * null_kv[h*DH + d];
    #pragma unroll
    for (int o=16;o>0;o>>=1) p += __shfl_down_sync(0xffffffffu, p, o);
    if ((threadIdx.x&31)==0) red[threadIdx.x>>5] = p;
    __syncthreads();
    const float x0 = 0.125f*(red[ql*2] + red[ql*2+1]);
    float m[NSPLIT], l[NSPLIT];
    size_t base[NSPLIT];
    #pragma unroll
    for (int sp=0;sp<NSPLIT;sp++){
        base[sp] = ((size_t)((b*HEADS+h)*NSPLIT + sp))*NQ + q;
        m[sp] = g_pm[base[sp]];
        l[sp] = g_pl[base[sp]];
    }
    float ms = x0;
    #pragma unroll
    for (int sp=0;sp<NSPLIT;sp++) ms = fmaxf(ms, m[sp]);
    float wn0 = __expf(x0-ms);
    float den = wn0, num = wn0 * null_kv[HDH + h*DH + d];
    #pragma unroll
    for (int sp=0;sp<NSPLIT;sp++){
        float wv = __expf(m[sp]-ms);
        den += l[sp]*wv;
        num += g_po[base[sp]*DH + d]*wv;
    }
    size_t off = ((size_t)(b*NQ)+q)*HDH + h*DH + d;
    g_ohh[off] = __float2half_rn(num/den);
}

// ---------------- routing: fixed point + radix top-k set selection --------
__global__ __launch_bounds__(1024) void k_route(){
    const int b = blockIdx.x, r = blockIdx.y;
    const int tid = threadIdx.x;
    const int cnt = (r==0) ? NQ : NKV;
    const float* s = g_s[r] + (size_t)b*SEQ;
    float sv[8];
    {
        float4 v0 = *(const float4*)(s + tid*8);
        float4 v1 = *(const float4*)(s + tid*8 + 4);
        sv[0]=v0.x; sv[1]=v0.y; sv[2]=v0.z; sv[3]=v0.w;
        sv[4]=v1.x; sv[5]=v1.y; sv[6]=v1.z; sv[7]=v1.w;
    }
    double E[8];
    #pragma unroll
    for (int i=0;i<8;i++) E[i] = exp((double)sv[i]);
    __shared__ double aSh;
    const double logk = (double)logf(r==0 ? 1152.0f : 2304.0f);
    double a = logk - (double)logf(8192.0f);
    for (int it=0; it<49; it++){
        double T = exp(-a);
        double tt=0.0;
        #pragma unroll
        for (int i=0;i<8;i++) tt += fmin(E[i], T);
        tt = blockSumD(tt);
        if (tid==0) aSh = logk - log(tt);
        __syncthreads();
        a = aSh;
        __syncthreads();
    }
    const float af = (float)a;
    uint32_t u[8];
    #pragma unroll
    for (int i=0;i<8;i++)
        u[i] = __float_as_uint(expf(fminf(sv[i]+af, 0.f)));
    __shared__ int hist[256];
    __shared__ uint32_t pbc; __shared__ int rbc;
    uint32_t prefix = 0; int remaining = cnt;
    for (int shift=24; shift>=0; shift-=8){
        for (int cc=tid; cc<256; cc+=1024) hist[cc]=0;
        __syncthreads();
        uint32_t pmask = (shift==24) ? 0u : (0xFFFFFFFFu << (shift+8));
        #pragma unroll
        for (int i=0;i<8;i++)
            if ((u[i] & pmask) == prefix)
                atomicAdd(&hist[(u[i]>>shift)&255], 1);
        __syncthreads();
        if (tid==0){
            int rem = remaining; uint32_t dig = 0;
            for (int d=255; d>=0; d--){
                int hv = hist[d];
                if (rem - hv <= 0){ dig = (uint32_t)d; break; }
                rem -= hv;
            }
            pbc = prefix | (dig<<shift);
            rbc = rem;
        }
        __syncthreads();
        prefix = pbc; remaining = rbc;
        __syncthreads();
    }
    const uint32_t ut = prefix;
    const int Cgt = cnt - remaining;
    __shared__ int sgt[1024], seqv[1024];
    int cgt=0, ceq=0;
    #pragma unroll
    for (int i=0;i<8;i++){
        if (u[i] > ut) cgt++;
        else if (u[i] == ut) ceq++;
    }
    sgt[tid]=cgt; seqv[tid]=ceq;
    __syncthreads();
    for (int off=1; off<1024; off<<=1){
        int a0=0,b0=0;
        if (tid>=off){ a0=sgt[tid-off]; b0=seqv[tid-off]; }
        __syncthreads();
        sgt[tid]+=a0; seqv[tid]+=b0;
        __syncthreads();
    }
    int gtPos = sgt[tid]-cgt;
    int eqPos = seqv[tid]-ceq;
    #pragma unroll
    for (int i=0;i<8;i++){
        const int idx = tid*8 + i;
        if (u[i] > ut){
            g_sel[r][b][gtPos++] = idx;
        } else if (u[i] == ut){
            int rk = eqPos++;
            if (rk < remaining) g_sel[r][b][Cgt + rk] = idx;
        }
    }
}

// ---------------- gather + rmsnorm (fp16 output) ----------------
__global__ __launch_bounds__(256) void k_gather(const float* __restrict__ x,
                                                const float* __restrict__ rms_g,
                                                int route){
    const int j = blockIdx.x, b = blockIdx.y;
    const int cnt = route ? NKV : NQ;
    __half* outh = route ? g_xkvnh : g_xqnh;
    const int n = g_sel[route][b][j];
    const float* xp = x + ((size_t)(b*SEQ) + n)*DIM;
    float ss=0.f;
    for (int d=threadIdx.x; d<DIM; d+=256){ float v=xp[d]; ss += v*v; }
    ss = blockSum(ss);
    const float sc = 32.f / fmaxf(sqrtf(ss), 1e-12f);
    size_t base = ((size_t)b*cnt + j)*DIM;
    for (int d=threadIdx.x; d<DIM; d+=256)
        outh[base+d] = __float2half_rn(xp[d]*sc*rms_g[d]);
}

// ---------------- scatter routed output ----------------
__global__ __launch_bounds__(256) void k_scatter(const float* __restrict__ null_q,
                                                 float* __restrict__ out){
    const int j=blockIdx.x, b=blockIdx.y;
    const int n = g_sel[0][b][j];
    float* op = out + ((size_t)(b*SEQ) + n)*DIM;
    const float* rp = g_ro + ((size_t)(b*NQ) + j)*DIM;
    for (int d=threadIdx.x; d<DIM; d+=256)
        op[d] += rp[d] - null_q[d];
}

// ---------------- launch ----------------
extern "C" void kernel_launch(void* const* d_in, const int* in_sizes, int n_in,
                              void* d_out, int out_size){
    (void)in_sizes; (void)n_in; (void)out_size;
    const float* x       = (const float*)d_in[0];
    const float* ln_g    = (const float*)d_in[1];
    const float* ln_b    = (const float*)d_in[2];
    const float* w_qkv_l = (const float*)d_in[3];
    const float* w_out_l = (const float*)d_in[4];
    const float* null_q  = (const float*)d_in[5];
    const float* rt_q    = (const float*)d_in[6];
    const float* rt_kv   = (const float*)d_in[7];
    const float* rms_g   = (const float*)d_in[8];
    const float* w_q_h   = (const float*)d_in[9];
    const float* w_kv_h  = (const float*)d_in[10];
    const float* null_kv = (const float*)d_in[11];
    const float* w_out_h = (const float*)d_in[12];
    float* out = (float*)d_out;

    float *p_ro;
    cudaGetSymbolAddress((void**)&p_ro, g_ro);
    __half *p_xnh,*p_qkvh,*p_loh,*p_xqnh,*p_xkvnh,*p_qhh,*p_kvhh,*p_ohh;
    __half *p_wqkv,*p_wol,*p_wqh,*p_wkvh,*p_woh;
    cudaGetSymbolAddress((void**)&p_xnh,   g_xnh);
    cudaGetSymbolAddress((void**)&p_qkvh,  g_qkvh);
    cudaGetSymbolAddress((void**)&p_loh,   g_loh);
    cudaGetSymbolAddress((void**)&p_xqnh,  g_xqnh);
    cudaGetSymbolAddress((void**)&p_xkvnh, g_xkvnh);
    cudaGetSymbolAddress((void**)&p_qhh,   g_qhh);
    cudaGetSymbolAddress((void**)&p_kvhh,  g_kvhh);
    cudaGetSymbolAddress((void**)&p_ohh,   g_ohh);
    cudaGetSymbolAddress((void**)&p_wqkv,  g_wqkv);
    cudaGetSymbolAddress((void**)&p_wol,   g_wol);
    cudaGetSymbolAddress((void**)&p_wqh,   g_wqh);
    cudaGetSymbolAddress((void**)&p_wkvh,  g_wkvh);
    cudaGetSymbolAddress((void**)&p_woh,   g_woh);

    cudaFuncSetAttribute(k_light,      cudaFuncAttributeMaxDynamicSharedMemorySize, LQ_SMEM);
    cudaFuncSetAttribute(k_heavy_part, cudaFuncAttributeMaxDynamicSharedMemorySize, HV_SMEM);
    cudaFuncSetAttribute(gemm_tc2,     cudaFuncAttributeMaxDynamicSharedMemorySize, GEMM_SMEM);

    // 0. weight conversions (fp16)
    k_cvtw<<<(DIM*3*HDH/4+255)/256, 256>>>(w_qkv_l, p_wqkv, DIM*3*HDH/4);
    k_cvtw<<<(HDH*DIM/4+255)/256,  256>>>(w_out_l, p_wol,  HDH*DIM/4);
    k_cvtw<<<(DIM*HDH/4+255)/256,  256>>>(w_q_h,   p_wqh,  DIM*HDH/4);
    k_cvtw<<<(DIM*2*HDH/4+255)/256,256>>>(w_kv_h,  p_wkvh, DIM*2*HDH/4);
    k_cvtw<<<(HDH*DIM/4+255)/256,  256>>>(w_out_h, p_woh,  HDH*DIM/4);
    // 1. layernorm + routing logits
    k_pre<<<NROWS, 256>>>(x, ln_g, ln_b, rt_q, rt_kv);
    // 2. light qkv projection (fp16 out)
    gemm_tc2<<<dim3(3*HDH/128, NROWS/128), 256, GEMM_SMEM>>>(NROWS, 3*HDH, DIM,
        p_xnh, p_wqkv, nullptr, p_qkvh, nullptr);
    // 3. routing
    k_route<<<dim3(BATCH,2), 1024>>>();
    // 4. windowed light attention (fp16 MMA)
    k_light<<<dim3(NW, HEADS, BATCH), 256, LQ_SMEM>>>();
    // 5. light output projection + null_q bias -> d_out (fp32 out)
    gemm_tc2<<<dim3(DIM/128, NROWS/128), 256, GEMM_SMEM>>>(NROWS, DIM, HDH,
        p_loh, p_wol, out, nullptr, null_q);
    // 6. gather + rmsnorm (fp16 out)
    k_gather<<<dim3(NQ,  BATCH), 256>>>(x, rms_g, 0);
    k_gather<<<dim3(NKV, BATCH), 256>>>(x, rms_g, 1);
    // 7. heavy projections (fp16 out)
    gemm_tc2<<<dim3(HDH/128,   BATCH*NQ/128),  256, GEMM_SMEM>>>(BATCH*NQ,  HDH,   DIM,
        p_xqnh, p_wqh, nullptr, p_qhh, nullptr);
    gemm_tc2<<<dim3(2*HDH/128, BATCH*NKV/128), 256, GEMM_SMEM>>>(BATCH*NKV, 2*HDH, DIM,
        p_xkvnh, p_wkvh, nullptr, p_kvhh, nullptr);
    // 8. heavy attention (fp16 MMA split-KV) + combine w/ null kv
    k_heavy_part<<<dim3(NQ/64, HEADS, BATCH*NSPLIT), 256, HV_SMEM>>>();
    k_heavy_comb<<<dim3(NQ/4, HEADS, BATCH), 256>>>(null_kv);
    // 9. heavy output projection (fp32 out)
    gemm_tc2<<<dim3(DIM/128, BATCH*NQ/128), 256, GEMM_SMEM>>>(BATCH*NQ, DIM, HDH,
        p_ohh, p_woh, p_ro, nullptr, nullptr);
    // 10. scatter
    k_scatter<<<dim3(NQ, BATCH), 256>>>(null_q, out);
}